// round 7
// baseline (speedup 1.0000x reference)
#include <cuda_runtime.h>
#include <cuda_bf16.h>
#include <math.h>
#include <stdint.h>

typedef unsigned int uint32;

#define NPTS 524288
#define TSZ  (1u << 19)
#define P1   2654435761u
#define P2   805459861u

#define KP0  96                        // layer-0 K padding (71 real cols)

// smem map (bytes): X region, Y region, B staging
#define HROW   528                     // H region row stride (16B-aligned, bank-permuting)
#define HARR   (64 * HROW)             // one hi or lo array: 33792
#define HREG   (2 * HARR)              // hi + lo: 67584
#define XREG   0
#define YREG   HREG
#define BST    (2 * HREG)              // 135168
#define BSTG   40960                   // one staging buf: Bh 256*80 + Bl 256*80
#define SMEM_SZ (BST + 2 * BSTG)       // 217088

// ---------------- weights (device globals; allocation-free rule) ----------------
// W0 rows k>=71 are BSS-zero and never written -> stay zero across replays.
__device__ __nv_bfloat16 g_W0hi[256 * KP0];
__device__ __nv_bfloat16 g_W0lo[256 * KP0];
__device__ __nv_bfloat16 g_W1hi[256 * 256];
__device__ __nv_bfloat16 g_W1lo[256 * 256];
__device__ __nv_bfloat16 g_W2hi[256 * 256];
__device__ __nv_bfloat16 g_W2lo[256 * 256];
__device__ float         g_w2last[256];

struct LevelParams { int R[16]; int dense[16]; };

// ---------------- PTX helpers ---------------------------------------------------
__device__ __forceinline__ uint32 smem_u32(const void* p) {
    uint32 a;
    asm("{ .reg .u64 t; cvta.to.shared.u64 t, %1; cvt.u32.u64 %0, t; }" : "=r"(a) : "l"(p));
    return a;
}

#define CP_ASYNC16(dst, src) asm volatile("cp.async.cg.shared.global [%0], [%1], 16;" :: "r"(dst), "l"(src))
#define CP_COMMIT()          asm volatile("cp.async.commit_group;" ::: "memory")
#define CP_WAIT(n)           asm volatile("cp.async.wait_group %0;" :: "n"(n) : "memory")

#define LDSM4(r0, r1, r2, r3, addr) \
    asm volatile("ldmatrix.sync.aligned.m8n8.x4.shared.b16 {%0,%1,%2,%3}, [%4];" \
                 : "=r"(r0), "=r"(r1), "=r"(r2), "=r"(r3) : "r"(addr))

#define MMA16816(d, a0, a1, a2, a3, b0, b1) \
    asm volatile("mma.sync.aligned.m16n8k16.row.col.f32.bf16.bf16.f32 " \
                 "{%0,%1,%2,%3}, {%4,%5,%6,%7}, {%8,%9}, {%0,%1,%2,%3};" \
                 : "+f"((d)[0]), "+f"((d)[1]), "+f"((d)[2]), "+f"((d)[3]) \
                 : "r"(a0), "r"(a1), "r"(a2), "r"(a3), "r"(b0), "r"(b1))

__device__ __forceinline__ void bf16_split(float v, __nv_bfloat16& hi, __nv_bfloat16& lo) {
    hi = __float2bfloat16(v);
    lo = __float2bfloat16(v - __bfloat162float(hi));
}

__device__ __forceinline__ float softplus100(float v) {
    float y = 100.f * v;
    if (y > 20.f) return v;
    return log1pf(__expf(y)) * 0.01f;
}

// ---------------- weight-norm fold + bf16 hi/lo split ---------------------------
__global__ void prep_weights_tc(const float* __restrict__ v, const float* __restrict__ g,
                                int Kdim, int KPAD,
                                __nv_bfloat16* __restrict__ Whi,
                                __nv_bfloat16* __restrict__ Wlo,
                                float* __restrict__ lastrow)
{
    int j = blockIdx.x;
    const float* vr = v + (size_t)j * Kdim;
    __shared__ float red[256];
    float s = 0.f;
    for (int k = threadIdx.x; k < Kdim; k += 256) { float t = vr[k]; s += t * t; }
    red[threadIdx.x] = s;
    __syncthreads();
    for (int st = 128; st > 0; st >>= 1) {
        if (threadIdx.x < st) red[threadIdx.x] += red[threadIdx.x + st];
        __syncthreads();
    }
    float scale = g[j] * rsqrtf(red[0]);
    if (lastrow != nullptr && j == 256) {
        for (int k = threadIdx.x; k < Kdim; k += 256) lastrow[k] = vr[k] * scale;
        return;
    }
    for (int k = threadIdx.x; k < Kdim; k += 256) {
        float w = vr[k] * scale;
        __nv_bfloat16 hi, lo;
        bf16_split(w, hi, lo);
        Whi[(size_t)j * KPAD + k] = hi;
        Wlo[(size_t)j * KPAD + k] = lo;
    }
}

// ---------------- fused MLP layer (device) ---------------------------------------
// A: smem region aReg (hi at +0, lo at +HARR), rows 64 x stride HROW.
// B: weights [256][KPAD] K-major hi/lo, streamed via double-buffered cp.async.
// Out: !LAST -> smem region oReg (hi/lo split, bias+softplus applied)
//       LAST -> gmem fp32 rows of 257, bias only.
template<int KPAD, bool ACT, bool LAST>
__device__ __forceinline__ void mlp_layer(uint32 sb, char* smemc,
    uint32 aReg, uint32 oReg,
    const char* __restrict__ Wh, const char* __restrict__ Wl,
    const float* __restrict__ bias,
    float* __restrict__ Of, int mBase, int tid, int lane, int wid)
{
    constexpr int NCH = KPAD / 32;
    const int warpM = wid & 1;        // 0..1 -> 32-row slice
    const int warpN = wid >> 1;       // 0..7 -> 32-col slice

    auto issueB = [&](int c) {
#pragma unroll
        for (int t = 0; t < 4; t++) {
            int j = tid + t * 512;            // 0..2047
            int arr = j >> 10;                // 0=hi 1=lo
            int rem = j & 1023;
            int row = rem >> 2, slot = rem & 3;
            const char* src = (arr ? Wl : Wh) + (size_t)row * (KPAD * 2) + c * 64 + slot * 16;
            CP_ASYNC16(sb + BST + (c & 1) * BSTG + arr * 20480 + row * 80 + slot * 16, src);
        }
        CP_COMMIT();
    };

    float acc[2][4][4];
#pragma unroll
    for (int mt = 0; mt < 2; mt++)
#pragma unroll
        for (int nt = 0; nt < 4; nt++)
#pragma unroll
            for (int q = 0; q < 4; q++) acc[mt][nt][q] = 0.f;

    // per-lane ldmatrix offsets
    const uint32 aLane = (uint32)(warpM * 32 + (lane & 15)) * HROW + (lane >> 4) * 16;
    const uint32 bLane = (uint32)(warpN * 32 + (lane & 7) + ((lane >> 4) << 3)) * 80
                         + ((lane >> 3) & 1) * 16;

    issueB(0);
    for (int c = 0; c < NCH; c++) {
        if (c + 1 < NCH) { issueB(c + 1); CP_WAIT(1); }
        else             { CP_WAIT(0); }
        __syncthreads();   // chunk c staged; prior-phase smem writes visible

        uint32 aBase = sb + aReg + aLane + c * 64;
        uint32 bBase = sb + BST + (c & 1) * BSTG + bLane;

#pragma unroll
        for (int ks = 0; ks < 2; ks++) {
            uint32 ka = aBase + ks * 32;
            uint32 kb = bBase + ks * 32;
            uint32 ah[2][4], al[2][4];
            LDSM4(ah[0][0], ah[0][1], ah[0][2], ah[0][3], ka);
            LDSM4(ah[1][0], ah[1][1], ah[1][2], ah[1][3], ka + 16 * HROW);
            LDSM4(al[0][0], al[0][1], al[0][2], al[0][3], ka + HARR);
            LDSM4(al[1][0], al[1][1], al[1][2], al[1][3], ka + HARR + 16 * HROW);
#pragma unroll
            for (int np = 0; np < 2; np++) {
                uint32 bh[4], bl[4];
                LDSM4(bh[0], bh[1], bh[2], bh[3], kb + np * 16 * 80);
                LDSM4(bl[0], bl[1], bl[2], bl[3], kb + 20480 + np * 16 * 80);
#pragma unroll
                for (int mt = 0; mt < 2; mt++) {
                    MMA16816(acc[mt][2 * np + 0], ah[mt][0], ah[mt][1], ah[mt][2], ah[mt][3], bh[0], bh[1]);
                    MMA16816(acc[mt][2 * np + 1], ah[mt][0], ah[mt][1], ah[mt][2], ah[mt][3], bh[2], bh[3]);
                    MMA16816(acc[mt][2 * np + 0], ah[mt][0], ah[mt][1], ah[mt][2], ah[mt][3], bl[0], bl[1]);
                    MMA16816(acc[mt][2 * np + 1], ah[mt][0], ah[mt][1], ah[mt][2], ah[mt][3], bl[2], bl[3]);
                    MMA16816(acc[mt][2 * np + 0], al[mt][0], al[mt][1], al[mt][2], al[mt][3], bh[0], bh[1]);
                    MMA16816(acc[mt][2 * np + 1], al[mt][0], al[mt][1], al[mt][2], al[mt][3], bh[2], bh[3]);
                }
            }
        }
        __syncthreads();   // compute c done -> buf c&1 may be refilled next iter
    }

    // epilogue
#pragma unroll
    for (int mt = 0; mt < 2; mt++) {
#pragma unroll
        for (int nt = 0; nt < 4; nt++) {
            int col = warpN * 32 + nt * 8 + (lane & 3) * 2;
            float bj0 = __ldg(bias + col), bj1 = __ldg(bias + col + 1);
#pragma unroll
            for (int half = 0; half < 2; half++) {
                int row = warpM * 32 + mt * 16 + (lane >> 2) + half * 8;
                float v0 = acc[mt][nt][2 * half + 0] + bj0;
                float v1 = acc[mt][nt][2 * half + 1] + bj1;
                if (ACT) { v0 = softplus100(v0); v1 = softplus100(v1); }
                if (LAST) {
                    float* orow = Of + (size_t)(mBase + row) * 257 + col;
                    orow[0] = v0; orow[1] = v1;
                } else {
                    __nv_bfloat16 h0, l0, h1, l1;
                    bf16_split(v0, h0, l0);
                    bf16_split(v1, h1, l1);
                    __nv_bfloat162 hv; hv.x = h0; hv.y = h1;
                    __nv_bfloat162 lv; lv.x = l0; lv.y = l1;
                    *(__nv_bfloat162*)(smemc + oReg + row * HROW + col * 2) = hv;
                    *(__nv_bfloat162*)(smemc + oReg + HARR + row * HROW + col * 2) = lv;
                }
            }
        }
    }
}

// ---------------- fused kernel: encode + 3 layers + last column ------------------
__global__ __launch_bounds__(512, 1)
void fused_kernel(const float* __restrict__ x, const float* __restrict__ tab,
                  const char* __restrict__ W0h, const char* __restrict__ W0l, const float* __restrict__ b0,
                  const char* __restrict__ W1h, const char* __restrict__ W1l, const float* __restrict__ b1,
                  const char* __restrict__ W2h, const char* __restrict__ W2l, const float* __restrict__ b2,
                  const float* __restrict__ w2last, float* __restrict__ out,
                  LevelParams lp)
{
    extern __shared__ char smemc[];
    uint32 sb = smem_u32(smemc);
    int tid = threadIdx.x, lane = tid & 31, wid = tid >> 5;
    int mBase = blockIdx.x * 64;

    // ---------------- encode phase: 8 threads per point -------------------------
    {
        int p = tid >> 3, sub = tid & 7;
        int gp = mBase + p;
        float px = x[3 * gp + 0], py = x[3 * gp + 1], pz = x[3 * gp + 2];
        __nv_bfloat16* Xh = (__nv_bfloat16*)(smemc + XREG + p * HROW);
        __nv_bfloat16* Xl = (__nv_bfloat16*)(smemc + XREG + HARR + p * HROW);

        auto put = [&](int c, float v) {
            __nv_bfloat16 hi, lo;
            bf16_split(v, hi, lo);
            Xh[c] = hi; Xl[c] = lo;
        };

        // pos-embed cols (0..38), strided by sub
        for (int c = sub; c < 39; c += 8) {
            float val;
            if (c < 3) val = (c == 0) ? px : ((c == 1) ? py : pz);
            else {
                int j = (c - 3) / 6, d = (c - 3) % 6;
                int dim = d % 3;
                float xi = (dim == 0) ? px : ((dim == 1) ? py : pz);
                float arg = (float)(1 << j) * xi;
                val = (d < 3) ? __sinf(arg) : __cosf(arg);
            }
            put(c, val);
        }

        // hash levels: 2 per thread
        float xc = fminf(fmaxf(px, 0.f), 1.f);
        float yc = fminf(fmaxf(py, 0.f), 1.f);
        float zc = fminf(fmaxf(pz, 0.f), 1.f);
        for (int l = sub; l < 16; l += 8) {
            int   R  = lp.R[l];
            float Rf = (float)R;
            float fx = xc * Rf, fy = yc * Rf, fz = zc * Rf;
            float f0x = floorf(fx), f0y = floorf(fy), f0z = floorf(fz);
            float w1x = fx - f0x, w1y = fy - f0y, w1z = fz - f0z;
            float wx[2] = {1.f - w1x, w1x};
            float wy[2] = {1.f - w1y, w1y};
            float wz[2] = {1.f - w1z, w1z};
            unsigned ux = (unsigned)f0x, uy = (unsigned)f0y, uz = (unsigned)f0z;
            unsigned Ru = (unsigned)R, R1 = Ru + 1u;
            int dns = lp.dense[l];
            const float2* tabL = (const float2*)tab + (size_t)l * TSZ;
            float ax = 0.f, ay = 0.f;
#pragma unroll
            for (int c = 0; c < 8; c++) {
                unsigned ox = c & 1, oy = (c >> 1) & 1, oz = (c >> 2) & 1;
                unsigned ix = min(ux + ox, Ru);
                unsigned iy = min(uy + oy, Ru);
                unsigned iz = min(uz + oz, Ru);
                unsigned flat;
                if (dns) flat = ix + R1 * (iy + R1 * iz);
                else     flat = (ix ^ (iy * P1) ^ (iz * P2)) & (TSZ - 1u);
                float wc = wx[ox] * wy[oy] * wz[oz];
                float2 tv = __ldg(&tabL[flat]);
                ax = fmaf(wc, tv.x, ax);
                ay = fmaf(wc, tv.y, ay);
            }
            put(39 + 2 * l, ax);
            put(40 + 2 * l, ay);
        }

        // zero pad cols 71..95 of X (layer-0 K padding)
        for (int idx = tid; idx < 64 * 25; idx += 512) {
            int row = idx / 25, c = 71 + idx % 25;
            __nv_bfloat16 z = __float2bfloat16(0.f);
            ((__nv_bfloat16*)(smemc + XREG + row * HROW))[c] = z;
            ((__nv_bfloat16*)(smemc + XREG + HARR + row * HROW))[c] = z;
        }
    }
    // (layer-0's first in-loop __syncthreads orders encode writes before reads)

    // ---------------- three layers (ping-pong X <-> Y) ---------------------------
    mlp_layer<KP0, true,  false>(sb, smemc, XREG, YREG, W0h, W0l, b0, nullptr, mBase, tid, lane, wid);
    mlp_layer<256, true,  false>(sb, smemc, YREG, XREG, W1h, W1l, b1, nullptr, mBase, tid, lane, wid);
    mlp_layer<256, false, true >(sb, smemc, XREG, 0,    W2h, W2l, b2, out,     mBase, tid, lane, wid);

    // ---------------- last output column from H1 (in X region) ------------------
    {
        int r = tid >> 3, grp = tid & 7;
        const __nv_bfloat16* hh = (const __nv_bfloat16*)(smemc + XREG + r * HROW);
        const __nv_bfloat16* hl = (const __nv_bfloat16*)(smemc + XREG + HARR + r * HROW);
        float s = 0.f;
#pragma unroll
        for (int q = 0; q < 32; q++) {
            int k = grp * 32 + q;
            float h = __bfloat162float(hh[k]) + __bfloat162float(hl[k]);
            s = fmaf(h, __ldg(w2last + k), s);
        }
#pragma unroll
        for (int o = 4; o > 0; o >>= 1) s += __shfl_down_sync(0xffffffffu, s, o, 8);
        if (grp == 0) out[(size_t)(mBase + r) * 257 + 256] = s + __ldg(b2 + 256);
    }
}

// ---------------- launch --------------------------------------------------------
extern "C" void kernel_launch(void* const* d_in, const int* in_sizes, int n_in,
                              void* d_out, int out_size)
{
    const float* x      = (const float*)d_in[0];
    const float* tables = (const float*)d_in[1];
    const float* v0 = (const float*)d_in[2];
    const float* g0 = (const float*)d_in[3];
    const float* b0 = (const float*)d_in[4];
    const float* v1 = (const float*)d_in[5];
    const float* g1 = (const float*)d_in[6];
    const float* b1 = (const float*)d_in[7];
    const float* v2 = (const float*)d_in[8];
    const float* g2 = (const float*)d_in[9];
    const float* b2 = (const float*)d_in[10];
    float* out = (float*)d_out;

    __nv_bfloat16 *W0hi, *W0lo, *W1hi, *W1lo, *W2hi, *W2lo;
    float* w2last;
    cudaGetSymbolAddress((void**)&W0hi, g_W0hi);
    cudaGetSymbolAddress((void**)&W0lo, g_W0lo);
    cudaGetSymbolAddress((void**)&W1hi, g_W1hi);
    cudaGetSymbolAddress((void**)&W1lo, g_W1lo);
    cudaGetSymbolAddress((void**)&W2hi, g_W2hi);
    cudaGetSymbolAddress((void**)&W2lo, g_W2lo);
    cudaGetSymbolAddress((void**)&w2last, g_w2last);

    LevelParams lp;
    double SCALE = pow(2.0, log2(2048.0 / 16.0) / 15.0);
    for (int l = 0; l < 16; l++) {
        int R = (int)ceil(16.0 * pow(SCALE, (double)l));
        lp.R[l] = R;
        long long cc = (long long)R + 1;
        lp.dense[l] = (cc * cc * cc <= (long long)TSZ) ? 1 : 0;
    }

    cudaFuncSetAttribute(fused_kernel, cudaFuncAttributeMaxDynamicSharedMemorySize, SMEM_SZ);

    prep_weights_tc<<<256, 256>>>(v0, g0, 71,  KP0, W0hi, W0lo, nullptr);
    prep_weights_tc<<<256, 256>>>(v1, g1, 256, 256, W1hi, W1lo, nullptr);
    prep_weights_tc<<<257, 256>>>(v2, g2, 256, 256, W2hi, W2lo, w2last);

    fused_kernel<<<NPTS / 64, 512, SMEM_SZ>>>(
        x, tables,
        (const char*)W0hi, (const char*)W0lo, b0,
        (const char*)W1hi, (const char*)W1lo, b1,
        (const char*)W2hi, (const char*)W2lo, b2,
        w2last, out, lp);
}

// round 9
// speedup vs baseline: 1.3513x; 1.3513x over previous
#include <cuda_runtime.h>
#include <cuda_bf16.h>
#include <math.h>
#include <stdint.h>

typedef unsigned int uint32;

#define NPTS 524288
#define TSZ  (1u << 19)
#define P1   2654435761u
#define P2   805459861u

#define KP0  96                        // layer-0 K padding (71 real cols)

// ---------------- scratch (device globals; allocation-free rule) ----------------
// Padding regions (cols 71..95 of F, rows k>=71 of W0) are BSS-zero and never
// written by any kernel, so they stay zero across graph replays.
__device__ __nv_bfloat16 g_Fhi [(size_t)NPTS * KP0];
__device__ __nv_bfloat16 g_Flo [(size_t)NPTS * KP0];
__device__ __nv_bfloat16 g_H0hi[(size_t)NPTS * 256];
__device__ __nv_bfloat16 g_H0lo[(size_t)NPTS * 256];
__device__ __nv_bfloat16 g_H1hi[(size_t)NPTS * 256];
__device__ __nv_bfloat16 g_H1lo[(size_t)NPTS * 256];
__device__ __nv_bfloat16 g_W0hi[256 * KP0];            // [N=256][Kpad] K-major
__device__ __nv_bfloat16 g_W0lo[256 * KP0];
__device__ __nv_bfloat16 g_W1hi[256 * 256];
__device__ __nv_bfloat16 g_W1lo[256 * 256];
__device__ __nv_bfloat16 g_W2hi[256 * 256];            // rows 0..255 of v2
__device__ __nv_bfloat16 g_W2lo[256 * 256];
__device__ float         g_w2last[256];                // row 256 of v2 (folded)

struct LevelParams { int R[16]; int dense[16]; };

// ---------------- PTX helpers ---------------------------------------------------
__device__ __forceinline__ uint32 smem_u32(const void* p) {
    uint32 a;
    asm("{ .reg .u64 t; cvta.to.shared.u64 t, %1; cvt.u32.u64 %0, t; }" : "=r"(a) : "l"(p));
    return a;
}

#define CP_ASYNC16(dst, src) asm volatile("cp.async.cg.shared.global [%0], [%1], 16;" :: "r"(dst), "l"(src))
#define CP_COMMIT()          asm volatile("cp.async.commit_group;" ::: "memory")
#define CP_WAIT(n)           asm volatile("cp.async.wait_group %0;" :: "n"(n) : "memory")

#define LDSM4(r0, r1, r2, r3, addr) \
    asm volatile("ldmatrix.sync.aligned.m8n8.x4.shared.b16 {%0,%1,%2,%3}, [%4];" \
                 : "=r"(r0), "=r"(r1), "=r"(r2), "=r"(r3) : "r"(addr))

#define MMA16816(d, a0, a1, a2, a3, b0, b1) \
    asm volatile("mma.sync.aligned.m16n8k16.row.col.f32.bf16.bf16.f32 " \
                 "{%0,%1,%2,%3}, {%4,%5,%6,%7}, {%8,%9}, {%0,%1,%2,%3};" \
                 : "+f"((d)[0]), "+f"((d)[1]), "+f"((d)[2]), "+f"((d)[3]) \
                 : "r"(a0), "r"(a1), "r"(a2), "r"(a3), "r"(b0), "r"(b1))

__device__ __forceinline__ void bf16_split(float v, __nv_bfloat16& hi, __nv_bfloat16& lo) {
    hi = __float2bfloat16(v);
    lo = __float2bfloat16(v - __bfloat162float(hi));
}

__device__ __forceinline__ float softplus100(float v) {
    float y = 100.f * v;
    if (y > 20.f) return v;
    return log1pf(__expf(y)) * 0.01f;
}

// ---------------- weight-norm fold + bf16 hi/lo split ---------------------------
__global__ void prep_weights_tc(const float* __restrict__ v, const float* __restrict__ g,
                                int Kdim, int KPAD,
                                __nv_bfloat16* __restrict__ Whi,
                                __nv_bfloat16* __restrict__ Wlo,
                                float* __restrict__ lastrow)
{
    int j = blockIdx.x;
    const float* vr = v + (size_t)j * Kdim;
    __shared__ float red[256];
    float s = 0.f;
    for (int k = threadIdx.x; k < Kdim; k += 256) { float t = vr[k]; s += t * t; }
    red[threadIdx.x] = s;
    __syncthreads();
    for (int st = 128; st > 0; st >>= 1) {
        if (threadIdx.x < st) red[threadIdx.x] += red[threadIdx.x + st];
        __syncthreads();
    }
    float scale = g[j] * rsqrtf(red[0]);
    if (lastrow != nullptr && j == 256) {
        for (int k = threadIdx.x; k < Kdim; k += 256) lastrow[k] = vr[k] * scale;
        return;
    }
    for (int k = threadIdx.x; k < Kdim; k += 256) {
        float w = vr[k] * scale;
        __nv_bfloat16 hi, lo;
        bf16_split(w, hi, lo);
        Whi[(size_t)j * KPAD + k] = hi;
        Wlo[(size_t)j * KPAD + k] = lo;
    }
}

// ---------------- encode: pos-embed + multires hash grid (bf16 hi/lo out) -------
__global__ void encode_kernel(const float* __restrict__ x,
                              const float* __restrict__ tab,
                              __nv_bfloat16* __restrict__ Fhi,
                              __nv_bfloat16* __restrict__ Flo,
                              LevelParams lp)
{
    int i = blockIdx.x * blockDim.x + threadIdx.x;
    if (i >= NPTS) return;
    float px = x[3 * i + 0], py = x[3 * i + 1], pz = x[3 * i + 2];

    float vals[72];
    vals[0] = px; vals[1] = py; vals[2] = pz;
#pragma unroll
    for (int j = 0; j < 6; j++) {
        float f = (float)(1 << j);
        float s0, c0, s1, c1, s2, c2;
        __sincosf(f * px, &s0, &c0);
        __sincosf(f * py, &s1, &c1);
        __sincosf(f * pz, &s2, &c2);
        vals[3 + 6 * j + 0] = s0; vals[3 + 6 * j + 1] = s1; vals[3 + 6 * j + 2] = s2;
        vals[3 + 6 * j + 3] = c0; vals[3 + 6 * j + 4] = c1; vals[3 + 6 * j + 5] = c2;
    }

    float xc = fminf(fmaxf(px, 0.f), 1.f);
    float yc = fminf(fmaxf(py, 0.f), 1.f);
    float zc = fminf(fmaxf(pz, 0.f), 1.f);

    for (int l = 0; l < 16; l++) {
        int   R  = lp.R[l];
        float Rf = (float)R;
        float fx = xc * Rf, fy = yc * Rf, fz = zc * Rf;
        float f0x = floorf(fx), f0y = floorf(fy), f0z = floorf(fz);
        float w1x = fx - f0x, w1y = fy - f0y, w1z = fz - f0z;
        float wx[2] = {1.f - w1x, w1x};
        float wy[2] = {1.f - w1y, w1y};
        float wz[2] = {1.f - w1z, w1z};
        unsigned ux = (unsigned)f0x, uy = (unsigned)f0y, uz = (unsigned)f0z;
        unsigned Ru = (unsigned)R, R1 = Ru + 1u;
        int dns = lp.dense[l];
        const float2* tabL = (const float2*)tab + (size_t)l * TSZ;
        float ax = 0.f, ay = 0.f;
#pragma unroll
        for (int c = 0; c < 8; c++) {
            unsigned ox = c & 1, oy = (c >> 1) & 1, oz = (c >> 2) & 1;
            unsigned ix = min(ux + ox, Ru);
            unsigned iy = min(uy + oy, Ru);
            unsigned iz = min(uz + oz, Ru);
            unsigned flat;
            if (dns) flat = ix + R1 * (iy + R1 * iz);
            else     flat = (ix ^ (iy * P1) ^ (iz * P2)) & (TSZ - 1u);
            float wc = wx[ox] * wy[oy] * wz[oz];
            float2 tv = __ldg(&tabL[flat]);
            ax = fmaf(wc, tv.x, ax);
            ay = fmaf(wc, tv.y, ay);
        }
        vals[39 + 2 * l] = ax;
        vals[40 + 2 * l] = ay;
    }

    // vectorized hi/lo store: 9 x uint4 per array (cols 0..71)
    __nv_bfloat16* Fh = Fhi + (size_t)i * KP0;
    __nv_bfloat16* Fl = Flo + (size_t)i * KP0;
#pragma unroll
    for (int c0 = 0; c0 < 72; c0 += 8) {
        uint32 hw[4], lw[4];
#pragma unroll
        for (int q = 0; q < 4; q++) {
            float a = vals[c0 + 2 * q], b = vals[c0 + 2 * q + 1];
            __nv_bfloat16 ha, la, hb, lb;
            bf16_split(a, ha, la);
            bf16_split(b, hb, lb);
            __nv_bfloat162 hv; hv.x = ha; hv.y = hb;
            __nv_bfloat162 lv; lv.x = la; lv.y = lb;
            hw[q] = *(uint32*)&hv;
            lw[q] = *(uint32*)&lv;
        }
        *(uint4*)(Fh + c0) = make_uint4(hw[0], hw[1], hw[2], hw[3]);
        *(uint4*)(Fl + c0) = make_uint4(lw[0], lw[1], lw[2], lw[3]);
    }
}

// ---------------- bf16 split GEMM via mma.sync (HMMA) ---------------------------
// CTA tile 64(M) x 128(N), 256 threads (8 warps of 16x64), 2-stage cp.async.
// 3 CTAs/SM -> 24 warps/SM for issue-slot fill. acc += AhBh + AhBl + AlBh.
#define KC   32
#define RS   80                        // smem row stride bytes (bank-permuting pad)
#define ATA  (64 * RS)                 // A tile array bytes  (5120)
#define ATB  (128 * RS)                // B tile array bytes  (10240)
#define STG  (2 * ATA + 2 * ATB)       // Ah, Al, Bh, Bl per stage (30720)
#define SMEM_SZ (2 * STG)              // 61440 -> 3 CTAs/SM

template<int KPAD, bool ACT, bool LAST>
__global__ __launch_bounds__(256, 3)
void gemm_mma(const __nv_bfloat16* __restrict__ Ah, const __nv_bfloat16* __restrict__ Al,
              const __nv_bfloat16* __restrict__ Bh, const __nv_bfloat16* __restrict__ Bl,
              const float* __restrict__ bias,
              __nv_bfloat16* __restrict__ Ohi, __nv_bfloat16* __restrict__ Olo,
              float* __restrict__ Of)
{
    constexpr int NC = KPAD / KC;
    extern __shared__ char smem[];
    uint32 sb = smem_u32(smem);

    const int tid  = threadIdx.x;
    const int lane = tid & 31;
    const int wid  = tid >> 5;
    const int warpM = wid & 3;         // 0..3 -> 16-row slice
    const int warpN = wid >> 2;        // 0..1 -> 64-col slice
    const int mBase = blockIdx.y * 64;
    const int nBase = blockIdx.x * 128;

    // global load mapping (16B chunks):
    //   A arrays: 64 rows x 4 slots = 256 -> 1 per thread
    //   B arrays: 128 rows x 4 slots = 512 -> 2 per thread
    const int ldRow = tid >> 2, ldSlot = tid & 3;

    const char* pAh = (const char*)(Ah + (size_t)mBase * KPAD);
    const char* pAl = (const char*)(Al + (size_t)mBase * KPAD);
    const char* pBh = (const char*)(Bh + (size_t)nBase * KPAD);
    const char* pBl = (const char*)(Bl + (size_t)nBase * KPAD);

    auto issue_chunk = [&](int c) {
        uint32 stage = sb + (c & 1) * STG;
        size_t ga  = (size_t)ldRow * (KPAD * 2) + c * (KC * 2) + ldSlot * 16;
        size_t gb0 = ga;                                        // B rows 0..63
        size_t gb1 = (size_t)(ldRow + 64) * (KPAD * 2) + c * (KC * 2) + ldSlot * 16;
        uint32 sa  = ldRow * RS + ldSlot * 16;
        uint32 sb0 = sa;
        uint32 sb1 = (ldRow + 64) * RS + ldSlot * 16;
        CP_ASYNC16(stage + sa,                    pAh + ga);
        CP_ASYNC16(stage + ATA + sa,              pAl + ga);
        CP_ASYNC16(stage + 2 * ATA + sb0,         pBh + gb0);
        CP_ASYNC16(stage + 2 * ATA + sb1,         pBh + gb1);
        CP_ASYNC16(stage + 2 * ATA + ATB + sb0,   pBl + gb0);
        CP_ASYNC16(stage + 2 * ATA + ATB + sb1,   pBl + gb1);
        CP_COMMIT();
    };

    float acc[8][4];
#pragma unroll
    for (int nt = 0; nt < 8; nt++)
#pragma unroll
        for (int q = 0; q < 4; q++) acc[nt][q] = 0.f;

    const uint32 aOff = (uint32)(warpM * 16 + (lane & 15)) * RS + (lane >> 4) * 16;
    const uint32 bOff = (uint32)(warpN * 64 + (lane & 7) + ((lane >> 4) << 3)) * RS
                        + ((lane >> 3) & 1) * 16;

    issue_chunk(0);

    for (int c = 0; c < NC; c++) {
        // sync ends compute of chunk c-1 (buffer (c+1)&1) -> safe to refill it
        __syncthreads();
        if (c + 1 < NC) { issue_chunk(c + 1); CP_WAIT(1); }
        else            { CP_WAIT(0); }

        uint32 stage = sb + (c & 1) * STG;
        uint32 sAh = stage + aOff;
        uint32 sAl = stage + ATA + aOff;
        uint32 sBh = stage + 2 * ATA + bOff;
        uint32 sBl = stage + 2 * ATA + ATB + bOff;

        // smem visibility of cp.async data needs a barrier after wait:
        __syncthreads();

#pragma unroll
        for (int ks = 0; ks < 2; ks++) {
            uint32 kb = ks * 32;               // 16 k-elems = 32 bytes
            uint32 ah[4], al[4];
            LDSM4(ah[0], ah[1], ah[2], ah[3], sAh + kb);
            LDSM4(al[0], al[1], al[2], al[3], sAl + kb);
#pragma unroll
            for (int np = 0; np < 4; np++) {
                uint32 bh[4], bl[4];
                LDSM4(bh[0], bh[1], bh[2], bh[3], sBh + np * 16 * RS + kb);
                LDSM4(bl[0], bl[1], bl[2], bl[3], sBl + np * 16 * RS + kb);
                MMA16816(acc[2 * np + 0], ah[0], ah[1], ah[2], ah[3], bh[0], bh[1]);
                MMA16816(acc[2 * np + 1], ah[0], ah[1], ah[2], ah[3], bh[2], bh[3]);
                MMA16816(acc[2 * np + 0], ah[0], ah[1], ah[2], ah[3], bl[0], bl[1]);
                MMA16816(acc[2 * np + 1], ah[0], ah[1], ah[2], ah[3], bl[2], bl[3]);
                MMA16816(acc[2 * np + 0], al[0], al[1], al[2], al[3], bh[0], bh[1]);
                MMA16816(acc[2 * np + 1], al[0], al[1], al[2], al[3], bh[2], bh[3]);
            }
        }
    }

    // ---------------- epilogue: bias + act + split + store ----------------------
#pragma unroll
    for (int nt = 0; nt < 8; nt++) {
        int n0 = nBase + warpN * 64 + nt * 8 + (lane & 3) * 2;
        float bj0 = __ldg(bias + n0), bj1 = __ldg(bias + n0 + 1);
#pragma unroll
        for (int half = 0; half < 2; half++) {
            int m = mBase + warpM * 16 + (lane >> 2) + half * 8;
            float v0 = acc[nt][2 * half + 0] + bj0;
            float v1 = acc[nt][2 * half + 1] + bj1;
            if (ACT) { v0 = softplus100(v0); v1 = softplus100(v1); }
            if (LAST) {
                float* orow = Of + (size_t)m * 257 + n0;
                orow[0] = v0; orow[1] = v1;
            } else {
                __nv_bfloat16 h0, l0, h1, l1;
                bf16_split(v0, h0, l0);
                bf16_split(v1, h1, l1);
                __nv_bfloat162 hv; hv.x = h0; hv.y = h1;
                __nv_bfloat162 lv; lv.x = l0; lv.y = l1;
                *(__nv_bfloat162*)(Ohi + (size_t)m * 256 + n0) = hv;
                *(__nv_bfloat162*)(Olo + (size_t)m * 256 + n0) = lv;
            }
        }
    }
}

// ---------------- last output column (row 256 of v2) ----------------------------
__global__ void lastcol_kernel(const __nv_bfloat16* __restrict__ Hhi,
                               const __nv_bfloat16* __restrict__ Hlo,
                               const float* __restrict__ wlast,
                               const float* __restrict__ b2,
                               float* __restrict__ out)
{
    __shared__ float w[256];
    int tid = threadIdx.x;
    w[tid] = wlast[tid];
    __syncthreads();
    int lane = tid & 31, warp = tid >> 5;
    size_t i = (size_t)blockIdx.x * 8 + warp;
    const __nv_bfloat16* hh = Hhi + i * 256;
    const __nv_bfloat16* hl = Hlo + i * 256;
    float s = 0.f;
#pragma unroll
    for (int q = 0; q < 8; q++) {
        int k = lane + 32 * q;
        float h = __bfloat162float(hh[k]) + __bfloat162float(hl[k]);
        s = fmaf(h, w[k], s);
    }
#pragma unroll
    for (int off = 16; off > 0; off >>= 1) s += __shfl_xor_sync(0xffffffffu, s, off);
    if (lane == 0) out[i * 257 + 256] = s + b2[256];
}

// ---------------- launch --------------------------------------------------------
extern "C" void kernel_launch(void* const* d_in, const int* in_sizes, int n_in,
                              void* d_out, int out_size)
{
    const float* x      = (const float*)d_in[0];
    const float* tables = (const float*)d_in[1];
    const float* v0 = (const float*)d_in[2];
    const float* g0 = (const float*)d_in[3];
    const float* b0 = (const float*)d_in[4];
    const float* v1 = (const float*)d_in[5];
    const float* g1 = (const float*)d_in[6];
    const float* b1 = (const float*)d_in[7];
    const float* v2 = (const float*)d_in[8];
    const float* g2 = (const float*)d_in[9];
    const float* b2 = (const float*)d_in[10];
    float* out = (float*)d_out;

    __nv_bfloat16 *Fhi, *Flo, *H0hi, *H0lo, *H1hi, *H1lo;
    __nv_bfloat16 *W0hi, *W0lo, *W1hi, *W1lo, *W2hi, *W2lo;
    float* w2last;
    cudaGetSymbolAddress((void**)&Fhi,  g_Fhi);
    cudaGetSymbolAddress((void**)&Flo,  g_Flo);
    cudaGetSymbolAddress((void**)&H0hi, g_H0hi);
    cudaGetSymbolAddress((void**)&H0lo, g_H0lo);
    cudaGetSymbolAddress((void**)&H1hi, g_H1hi);
    cudaGetSymbolAddress((void**)&H1lo, g_H1lo);
    cudaGetSymbolAddress((void**)&W0hi, g_W0hi);
    cudaGetSymbolAddress((void**)&W0lo, g_W0lo);
    cudaGetSymbolAddress((void**)&W1hi, g_W1hi);
    cudaGetSymbolAddress((void**)&W1lo, g_W1lo);
    cudaGetSymbolAddress((void**)&W2hi, g_W2hi);
    cudaGetSymbolAddress((void**)&W2lo, g_W2lo);
    cudaGetSymbolAddress((void**)&w2last, g_w2last);

    LevelParams lp;
    double SCALE = pow(2.0, log2(2048.0 / 16.0) / 15.0);
    for (int l = 0; l < 16; l++) {
        int R = (int)ceil(16.0 * pow(SCALE, (double)l));
        lp.R[l] = R;
        long long cc = (long long)R + 1;
        lp.dense[l] = (cc * cc * cc <= (long long)TSZ) ? 1 : 0;
    }

    cudaFuncSetAttribute(gemm_mma<KP0, true,  false>, cudaFuncAttributeMaxDynamicSharedMemorySize, SMEM_SZ);
    cudaFuncSetAttribute(gemm_mma<256, true,  false>, cudaFuncAttributeMaxDynamicSharedMemorySize, SMEM_SZ);
    cudaFuncSetAttribute(gemm_mma<256, false, true >, cudaFuncAttributeMaxDynamicSharedMemorySize, SMEM_SZ);

    prep_weights_tc<<<256, 256>>>(v0, g0, 71,  KP0, W0hi, W0lo, nullptr);
    prep_weights_tc<<<256, 256>>>(v1, g1, 256, 256, W1hi, W1lo, nullptr);
    prep_weights_tc<<<257, 256>>>(v2, g2, 256, 256, W2hi, W2lo, w2last);

    encode_kernel<<<NPTS / 256, 256>>>(x, tables, Fhi, Flo, lp);

    dim3 grid(2, NPTS / 64);
    gemm_mma<KP0, true,  false><<<grid, 256, SMEM_SZ>>>(Fhi,  Flo,  W0hi, W0lo, b0, H0hi, H0lo, nullptr);
    gemm_mma<256, true,  false><<<grid, 256, SMEM_SZ>>>(H0hi, H0lo, W1hi, W1lo, b1, H1hi, H1lo, nullptr);
    gemm_mma<256, false, true ><<<grid, 256, SMEM_SZ>>>(H1hi, H1lo, W2hi, W2lo, b2, nullptr, nullptr, out);

    lastcol_kernel<<<NPTS / 8, 256>>>(H1hi, H1lo, w2last, b2, out);
}

// round 10
// speedup vs baseline: 1.4528x; 1.0751x over previous
#include <cuda_runtime.h>
#include <cuda_bf16.h>
#include <math.h>
#include <stdint.h>

typedef unsigned int uint32;

#define NPTS 524288
#define TSZ  (1u << 19)
#define P1   2654435761u
#define P2   805459861u

#define KP0  96                        // layer-0 K padding (71 real cols)

// ---------------- scratch (device globals; allocation-free rule) ----------------
// Padding regions (cols 71..95 of F, rows k>=71 of W0) are BSS-zero and never
// written by any kernel, so they stay zero across graph replays.
__device__ __nv_bfloat16 g_Fhi [(size_t)NPTS * KP0];
__device__ __nv_bfloat16 g_Flo [(size_t)NPTS * KP0];
__device__ __nv_bfloat16 g_H0hi[(size_t)NPTS * 256];
__device__ __nv_bfloat16 g_H0lo[(size_t)NPTS * 256];
__device__ __nv_bfloat16 g_H1hi[(size_t)NPTS * 256];
__device__ __nv_bfloat16 g_H1lo[(size_t)NPTS * 256];
__device__ __nv_bfloat16 g_W0hi[256 * KP0];            // [N=256][Kpad] K-major
__device__ __nv_bfloat16 g_W0lo[256 * KP0];
__device__ __nv_bfloat16 g_W1hi[256 * 256];
__device__ __nv_bfloat16 g_W1lo[256 * 256];
__device__ __nv_bfloat16 g_W2hi[256 * 256];            // rows 0..255 of v2
__device__ __nv_bfloat16 g_W2lo[256 * 256];
__device__ float         g_w2last[256];                // row 256 of v2 (folded)

struct LevelParams { int R[16]; int dense[16]; };

// ---------------- PTX helpers ---------------------------------------------------
__device__ __forceinline__ uint32 smem_u32(const void* p) {
    uint32 a;
    asm("{ .reg .u64 t; cvta.to.shared.u64 t, %1; cvt.u32.u64 %0, t; }" : "=r"(a) : "l"(p));
    return a;
}

#define CP_ASYNC16(dst, src) asm volatile("cp.async.cg.shared.global [%0], [%1], 16;" :: "r"(dst), "l"(src))
#define CP_COMMIT()          asm volatile("cp.async.commit_group;" ::: "memory")
#define CP_WAIT(n)           asm volatile("cp.async.wait_group %0;" :: "n"(n) : "memory")

#define LDSM4(r0, r1, r2, r3, addr) \
    asm volatile("ldmatrix.sync.aligned.m8n8.x4.shared.b16 {%0,%1,%2,%3}, [%4];" \
                 : "=r"(r0), "=r"(r1), "=r"(r2), "=r"(r3) : "r"(addr))

#define MMA16816(d, a0, a1, a2, a3, b0, b1) \
    asm volatile("mma.sync.aligned.m16n8k16.row.col.f32.bf16.bf16.f32 " \
                 "{%0,%1,%2,%3}, {%4,%5,%6,%7}, {%8,%9}, {%0,%1,%2,%3};" \
                 : "+f"((d)[0]), "+f"((d)[1]), "+f"((d)[2]), "+f"((d)[3]) \
                 : "r"(a0), "r"(a1), "r"(a2), "r"(a3), "r"(b0), "r"(b1))

__device__ __forceinline__ void bf16_split(float v, __nv_bfloat16& hi, __nv_bfloat16& lo) {
    hi = __float2bfloat16(v);
    lo = __float2bfloat16(v - __bfloat162float(hi));
}

__device__ __forceinline__ float softplus100(float v) {
    float y = 100.f * v;
    if (y > 20.f) return v;
    return log1pf(__expf(y)) * 0.01f;
}

// ---------------- weight-norm fold + bf16 hi/lo split ---------------------------
__global__ void prep_weights_tc(const float* __restrict__ v, const float* __restrict__ g,
                                int Kdim, int KPAD,
                                __nv_bfloat16* __restrict__ Whi,
                                __nv_bfloat16* __restrict__ Wlo,
                                float* __restrict__ lastrow)
{
    int j = blockIdx.x;
    const float* vr = v + (size_t)j * Kdim;
    __shared__ float red[256];
    float s = 0.f;
    for (int k = threadIdx.x; k < Kdim; k += 256) { float t = vr[k]; s += t * t; }
    red[threadIdx.x] = s;
    __syncthreads();
    for (int st = 128; st > 0; st >>= 1) {
        if (threadIdx.x < st) red[threadIdx.x] += red[threadIdx.x + st];
        __syncthreads();
    }
    float scale = g[j] * rsqrtf(red[0]);
    if (lastrow != nullptr && j == 256) {
        for (int k = threadIdx.x; k < Kdim; k += 256) lastrow[k] = vr[k] * scale;
        return;
    }
    for (int k = threadIdx.x; k < Kdim; k += 256) {
        float w = vr[k] * scale;
        __nv_bfloat16 hi, lo;
        bf16_split(w, hi, lo);
        Whi[(size_t)j * KPAD + k] = hi;
        Wlo[(size_t)j * KPAD + k] = lo;
    }
}

// ---------------- encode: pos-embed + multires hash grid (bf16 hi/lo out) -------
__global__ void encode_kernel(const float* __restrict__ x,
                              const float* __restrict__ tab,
                              __nv_bfloat16* __restrict__ Fhi,
                              __nv_bfloat16* __restrict__ Flo,
                              LevelParams lp)
{
    int i = blockIdx.x * blockDim.x + threadIdx.x;
    if (i >= NPTS) return;
    float px = x[3 * i + 0], py = x[3 * i + 1], pz = x[3 * i + 2];

    float vals[72];
    vals[0] = px; vals[1] = py; vals[2] = pz;
#pragma unroll
    for (int j = 0; j < 6; j++) {
        float f = (float)(1 << j);
        float s0, c0, s1, c1, s2, c2;
        __sincosf(f * px, &s0, &c0);
        __sincosf(f * py, &s1, &c1);
        __sincosf(f * pz, &s2, &c2);
        vals[3 + 6 * j + 0] = s0; vals[3 + 6 * j + 1] = s1; vals[3 + 6 * j + 2] = s2;
        vals[3 + 6 * j + 3] = c0; vals[3 + 6 * j + 4] = c1; vals[3 + 6 * j + 5] = c2;
    }

    float xc = fminf(fmaxf(px, 0.f), 1.f);
    float yc = fminf(fmaxf(py, 0.f), 1.f);
    float zc = fminf(fmaxf(pz, 0.f), 1.f);

    for (int l = 0; l < 16; l++) {
        int   R  = lp.R[l];
        float Rf = (float)R;
        float fx = xc * Rf, fy = yc * Rf, fz = zc * Rf;
        float f0x = floorf(fx), f0y = floorf(fy), f0z = floorf(fz);
        float w1x = fx - f0x, w1y = fy - f0y, w1z = fz - f0z;
        float wx[2] = {1.f - w1x, w1x};
        float wy[2] = {1.f - w1y, w1y};
        float wz[2] = {1.f - w1z, w1z};
        unsigned ux = (unsigned)f0x, uy = (unsigned)f0y, uz = (unsigned)f0z;
        unsigned Ru = (unsigned)R, R1 = Ru + 1u;
        int dns = lp.dense[l];
        const float2* tabL = (const float2*)tab + (size_t)l * TSZ;
        float ax = 0.f, ay = 0.f;
#pragma unroll
        for (int c = 0; c < 8; c++) {
            unsigned ox = c & 1, oy = (c >> 1) & 1, oz = (c >> 2) & 1;
            unsigned ix = min(ux + ox, Ru);
            unsigned iy = min(uy + oy, Ru);
            unsigned iz = min(uz + oz, Ru);
            unsigned flat;
            if (dns) flat = ix + R1 * (iy + R1 * iz);
            else     flat = (ix ^ (iy * P1) ^ (iz * P2)) & (TSZ - 1u);
            float wc = wx[ox] * wy[oy] * wz[oz];
            float2 tv = __ldg(&tabL[flat]);
            ax = fmaf(wc, tv.x, ax);
            ay = fmaf(wc, tv.y, ay);
        }
        vals[39 + 2 * l] = ax;
        vals[40 + 2 * l] = ay;
    }

    // vectorized hi/lo store: 9 x uint4 per array (cols 0..71)
    __nv_bfloat16* Fh = Fhi + (size_t)i * KP0;
    __nv_bfloat16* Fl = Flo + (size_t)i * KP0;
#pragma unroll
    for (int c0 = 0; c0 < 72; c0 += 8) {
        uint32 hw[4], lw[4];
#pragma unroll
        for (int q = 0; q < 4; q++) {
            float a = vals[c0 + 2 * q], b = vals[c0 + 2 * q + 1];
            __nv_bfloat16 ha, la, hb, lb;
            bf16_split(a, ha, la);
            bf16_split(b, hb, lb);
            __nv_bfloat162 hv; hv.x = ha; hv.y = hb;
            __nv_bfloat162 lv; lv.x = la; lv.y = lb;
            hw[q] = *(uint32*)&hv;
            lw[q] = *(uint32*)&lv;
        }
        *(uint4*)(Fh + c0) = make_uint4(hw[0], hw[1], hw[2], hw[3]);
        *(uint4*)(Fl + c0) = make_uint4(lw[0], lw[1], lw[2], lw[3]);
    }
}

// ---------------- bf16 split GEMM via mma.sync (HMMA) ---------------------------
// CTA tile 128(M) x 128(N), 256 threads (8 warps of 32x64), 2-stage cp.async,
// ONE __syncthreads per K-chunk (cutlass order: wait -> sync -> issue -> compute).
// acc += AhBh + AhBl + AlBh.
#define KC   32
#define RS   80                        // smem row stride bytes (bank-permuting pad)
#define ATB  (128 * RS)                // 10240 bytes per tile array
#define STG  (4 * ATB)                 // Ah, Al, Bh, Bl per stage (40960)
#define SMEM_SZ (2 * STG)              // 81920 -> 2 CTAs/SM

template<int KPAD, bool ACT, bool LAST>
__global__ __launch_bounds__(256, 2)
void gemm_mma(const __nv_bfloat16* __restrict__ Ah, const __nv_bfloat16* __restrict__ Al,
              const __nv_bfloat16* __restrict__ Bh, const __nv_bfloat16* __restrict__ Bl,
              const float* __restrict__ bias,
              __nv_bfloat16* __restrict__ Ohi, __nv_bfloat16* __restrict__ Olo,
              float* __restrict__ Of)
{
    constexpr int NC = KPAD / KC;
    extern __shared__ char smem[];
    uint32 sb = smem_u32(smem);

    const int tid  = threadIdx.x;
    const int lane = tid & 31;
    const int wid  = tid >> 5;
    const int warpM = wid & 3;         // 0..3 -> 32-row slice
    const int warpN = wid >> 2;        // 0..1 -> 64-col slice
    const int mBase = blockIdx.y * 128;
    const int nBase = blockIdx.x * 128;

    // global load mapping: per array 512 x 16B transfers; thread does idx, idx+256
    const int ldRow0 = tid >> 2, ldSlot = tid & 3;
    const int ldRow1 = ldRow0 + 64;

    const char* pAh = (const char*)(Ah + (size_t)mBase * KPAD);
    const char* pAl = (const char*)(Al + (size_t)mBase * KPAD);
    const char* pBh = (const char*)(Bh + (size_t)nBase * KPAD);
    const char* pBl = (const char*)(Bl + (size_t)nBase * KPAD);

    auto issue_chunk = [&](int c) {
        uint32 stage = sb + (c & 1) * STG;
        size_t gofs0 = (size_t)ldRow0 * (KPAD * 2) + c * (KC * 2) + ldSlot * 16;
        size_t gofs1 = (size_t)ldRow1 * (KPAD * 2) + c * (KC * 2) + ldSlot * 16;
        uint32 sofs0 = ldRow0 * RS + ldSlot * 16;
        uint32 sofs1 = ldRow1 * RS + ldSlot * 16;
        CP_ASYNC16(stage + 0 * ATB + sofs0, pAh + gofs0);
        CP_ASYNC16(stage + 0 * ATB + sofs1, pAh + gofs1);
        CP_ASYNC16(stage + 1 * ATB + sofs0, pAl + gofs0);
        CP_ASYNC16(stage + 1 * ATB + sofs1, pAl + gofs1);
        CP_ASYNC16(stage + 2 * ATB + sofs0, pBh + gofs0);
        CP_ASYNC16(stage + 2 * ATB + sofs1, pBh + gofs1);
        CP_ASYNC16(stage + 3 * ATB + sofs0, pBl + gofs0);
        CP_ASYNC16(stage + 3 * ATB + sofs1, pBl + gofs1);
        CP_COMMIT();
    };

    float acc[2][8][4];
#pragma unroll
    for (int mt = 0; mt < 2; mt++)
#pragma unroll
        for (int nt = 0; nt < 8; nt++)
#pragma unroll
            for (int q = 0; q < 4; q++) acc[mt][nt][q] = 0.f;

    const uint32 aOff = (uint32)(warpM * 32 + (lane & 15)) * RS + (lane >> 4) * 16;
    const uint32 bOff = (uint32)(warpN * 64 + (lane & 7) + ((lane >> 4) << 3)) * RS
                        + ((lane >> 3) & 1) * 16;

    issue_chunk(0);

    for (int c = 0; c < NC; c++) {
        // chunk c is the only group in flight at this point; wait for it, then
        // the barrier (a) publishes its smem data to all threads and (b) marks
        // that every warp finished computing chunk c-1, so buffer (c+1)&1 is free.
        CP_WAIT(0);
        __syncthreads();
        if (c + 1 < NC) issue_chunk(c + 1);   // overlaps compute of chunk c

        uint32 stage = sb + (c & 1) * STG;
        uint32 sAh = stage + aOff;
        uint32 sAl = stage + ATB + aOff;
        uint32 sBh = stage + 2 * ATB + bOff;
        uint32 sBl = stage + 3 * ATB + bOff;

#pragma unroll
        for (int ks = 0; ks < 2; ks++) {
            uint32 kb = ks * 32;               // 16 k-elems = 32 bytes
            uint32 ah[2][4], al[2][4];
            LDSM4(ah[0][0], ah[0][1], ah[0][2], ah[0][3], sAh + kb);
            LDSM4(ah[1][0], ah[1][1], ah[1][2], ah[1][3], sAh + 16 * RS + kb);
            LDSM4(al[0][0], al[0][1], al[0][2], al[0][3], sAl + kb);
            LDSM4(al[1][0], al[1][1], al[1][2], al[1][3], sAl + 16 * RS + kb);
#pragma unroll
            for (int np = 0; np < 4; np++) {
                uint32 bh[4], bl[4];
                LDSM4(bh[0], bh[1], bh[2], bh[3], sBh + np * 16 * RS + kb);
                LDSM4(bl[0], bl[1], bl[2], bl[3], sBl + np * 16 * RS + kb);
#pragma unroll
                for (int mt = 0; mt < 2; mt++) {
                    MMA16816(acc[mt][2 * np + 0], ah[mt][0], ah[mt][1], ah[mt][2], ah[mt][3], bh[0], bh[1]);
                    MMA16816(acc[mt][2 * np + 1], ah[mt][0], ah[mt][1], ah[mt][2], ah[mt][3], bh[2], bh[3]);
                    MMA16816(acc[mt][2 * np + 0], ah[mt][0], ah[mt][1], ah[mt][2], ah[mt][3], bl[0], bl[1]);
                    MMA16816(acc[mt][2 * np + 1], ah[mt][0], ah[mt][1], ah[mt][2], ah[mt][3], bl[2], bl[3]);
                    MMA16816(acc[mt][2 * np + 0], al[mt][0], al[mt][1], al[mt][2], al[mt][3], bh[0], bh[1]);
                    MMA16816(acc[mt][2 * np + 1], al[mt][0], al[mt][1], al[mt][2], al[mt][3], bh[2], bh[3]);
                }
            }
        }
    }

    // ---------------- epilogue: bias + act + split + store ----------------------
#pragma unroll
    for (int mt = 0; mt < 2; mt++) {
        int m0 = mBase + warpM * 32 + mt * 16 + (lane >> 2);
#pragma unroll
        for (int nt = 0; nt < 8; nt++) {
            int n0 = nBase + warpN * 64 + nt * 8 + (lane & 3) * 2;
            float bj0 = __ldg(bias + n0), bj1 = __ldg(bias + n0 + 1);
#pragma unroll
            for (int half = 0; half < 2; half++) {
                int m = m0 + half * 8;
                float v0 = acc[mt][nt][2 * half + 0] + bj0;
                float v1 = acc[mt][nt][2 * half + 1] + bj1;
                if (ACT) { v0 = softplus100(v0); v1 = softplus100(v1); }
                if (LAST) {
                    float* orow = Of + (size_t)m * 257 + n0;
                    orow[0] = v0; orow[1] = v1;
                } else {
                    __nv_bfloat16 h0, l0, h1, l1;
                    bf16_split(v0, h0, l0);
                    bf16_split(v1, h1, l1);
                    __nv_bfloat162 hv; hv.x = h0; hv.y = h1;
                    __nv_bfloat162 lv; lv.x = l0; lv.y = l1;
                    *(__nv_bfloat162*)(Ohi + (size_t)m * 256 + n0) = hv;
                    *(__nv_bfloat162*)(Olo + (size_t)m * 256 + n0) = lv;
                }
            }
        }
    }
}

// ---------------- last output column (row 256 of v2) ----------------------------
__global__ void lastcol_kernel(const __nv_bfloat16* __restrict__ Hhi,
                               const __nv_bfloat16* __restrict__ Hlo,
                               const float* __restrict__ wlast,
                               const float* __restrict__ b2,
                               float* __restrict__ out)
{
    __shared__ float w[256];
    int tid = threadIdx.x;
    w[tid] = wlast[tid];
    __syncthreads();
    int lane = tid & 31, warp = tid >> 5;
    size_t i = (size_t)blockIdx.x * 8 + warp;
    const __nv_bfloat16* hh = Hhi + i * 256;
    const __nv_bfloat16* hl = Hlo + i * 256;
    float s = 0.f;
#pragma unroll
    for (int q = 0; q < 8; q++) {
        int k = lane + 32 * q;
        float h = __bfloat162float(hh[k]) + __bfloat162float(hl[k]);
        s = fmaf(h, w[k], s);
    }
#pragma unroll
    for (int off = 16; off > 0; off >>= 1) s += __shfl_xor_sync(0xffffffffu, s, off);
    if (lane == 0) out[i * 257 + 256] = s + b2[256];
}

// ---------------- launch --------------------------------------------------------
extern "C" void kernel_launch(void* const* d_in, const int* in_sizes, int n_in,
                              void* d_out, int out_size)
{
    const float* x      = (const float*)d_in[0];
    const float* tables = (const float*)d_in[1];
    const float* v0 = (const float*)d_in[2];
    const float* g0 = (const float*)d_in[3];
    const float* b0 = (const float*)d_in[4];
    const float* v1 = (const float*)d_in[5];
    const float* g1 = (const float*)d_in[6];
    const float* b1 = (const float*)d_in[7];
    const float* v2 = (const float*)d_in[8];
    const float* g2 = (const float*)d_in[9];
    const float* b2 = (const float*)d_in[10];
    float* out = (float*)d_out;

    __nv_bfloat16 *Fhi, *Flo, *H0hi, *H0lo, *H1hi, *H1lo;
    __nv_bfloat16 *W0hi, *W0lo, *W1hi, *W1lo, *W2hi, *W2lo;
    float* w2last;
    cudaGetSymbolAddress((void**)&Fhi,  g_Fhi);
    cudaGetSymbolAddress((void**)&Flo,  g_Flo);
    cudaGetSymbolAddress((void**)&H0hi, g_H0hi);
    cudaGetSymbolAddress((void**)&H0lo, g_H0lo);
    cudaGetSymbolAddress((void**)&H1hi, g_H1hi);
    cudaGetSymbolAddress((void**)&H1lo, g_H1lo);
    cudaGetSymbolAddress((void**)&W0hi, g_W0hi);
    cudaGetSymbolAddress((void**)&W0lo, g_W0lo);
    cudaGetSymbolAddress((void**)&W1hi, g_W1hi);
    cudaGetSymbolAddress((void**)&W1lo, g_W1lo);
    cudaGetSymbolAddress((void**)&W2hi, g_W2hi);
    cudaGetSymbolAddress((void**)&W2lo, g_W2lo);
    cudaGetSymbolAddress((void**)&w2last, g_w2last);

    LevelParams lp;
    double SCALE = pow(2.0, log2(2048.0 / 16.0) / 15.0);
    for (int l = 0; l < 16; l++) {
        int R = (int)ceil(16.0 * pow(SCALE, (double)l));
        lp.R[l] = R;
        long long cc = (long long)R + 1;
        lp.dense[l] = (cc * cc * cc <= (long long)TSZ) ? 1 : 0;
    }

    cudaFuncSetAttribute(gemm_mma<KP0, true,  false>, cudaFuncAttributeMaxDynamicSharedMemorySize, SMEM_SZ);
    cudaFuncSetAttribute(gemm_mma<256, true,  false>, cudaFuncAttributeMaxDynamicSharedMemorySize, SMEM_SZ);
    cudaFuncSetAttribute(gemm_mma<256, false, true >, cudaFuncAttributeMaxDynamicSharedMemorySize, SMEM_SZ);

    prep_weights_tc<<<256, 256>>>(v0, g0, 71,  KP0, W0hi, W0lo, nullptr);
    prep_weights_tc<<<256, 256>>>(v1, g1, 256, 256, W1hi, W1lo, nullptr);
    prep_weights_tc<<<257, 256>>>(v2, g2, 256, 256, W2hi, W2lo, w2last);

    encode_kernel<<<NPTS / 256, 256>>>(x, tables, Fhi, Flo, lp);

    dim3 grid(2, NPTS / 128);
    gemm_mma<KP0, true,  false><<<grid, 256, SMEM_SZ>>>(Fhi,  Flo,  W0hi, W0lo, b0, H0hi, H0lo, nullptr);
    gemm_mma<256, true,  false><<<grid, 256, SMEM_SZ>>>(H0hi, H0lo, W1hi, W1lo, b1, H1hi, H1lo, nullptr);
    gemm_mma<256, false, true ><<<grid, 256, SMEM_SZ>>>(H1hi, H1lo, W2hi, W2lo, b2, nullptr, nullptr, out);

    lastcol_kernel<<<NPTS / 8, 256>>>(H1hi, H1lo, w2last, b2, out);
}

// round 11
// speedup vs baseline: 2.2688x; 1.5617x over previous
#include <cuda_runtime.h>
#include <cuda_fp16.h>
#include <math.h>
#include <stdint.h>

typedef unsigned int uint32;

#define NPTS 524288
#define TSZ  (1u << 19)
#define P1   2654435761u
#define P2   805459861u

#define KP0  96                        // layer-0 K padding (71 real cols)

// ---------------- scratch (device globals; allocation-free rule) ----------------
// Padding regions (cols 71..95 of F, rows k>=71 of W0) are BSS-zero (fp16 +0.0)
// and never written by any kernel, so they stay zero across graph replays.
__device__ __half g_F [(size_t)NPTS * KP0];
__device__ __half g_H0[(size_t)NPTS * 256];
__device__ __half g_H1[(size_t)NPTS * 256];
__device__ __half g_W0[256 * KP0];             // [N=256][Kpad] K-major
__device__ __half g_W1[256 * 256];
__device__ __half g_W2[256 * 256];             // rows 0..255 of v2
__device__ float  g_w2last[256];               // row 256 of v2 (folded)

struct LevelParams { int R[16]; int dense[16]; };

// ---------------- PTX helpers ---------------------------------------------------
__device__ __forceinline__ uint32 smem_u32(const void* p) {
    uint32 a;
    asm("{ .reg .u64 t; cvta.to.shared.u64 t, %1; cvt.u32.u64 %0, t; }" : "=r"(a) : "l"(p));
    return a;
}

#define CP_ASYNC16(dst, src) asm volatile("cp.async.cg.shared.global [%0], [%1], 16;" :: "r"(dst), "l"(src))
#define CP_COMMIT()          asm volatile("cp.async.commit_group;" ::: "memory")
#define CP_WAIT(n)           asm volatile("cp.async.wait_group %0;" :: "n"(n) : "memory")

#define LDSM4(r0, r1, r2, r3, addr) \
    asm volatile("ldmatrix.sync.aligned.m8n8.x4.shared.b16 {%0,%1,%2,%3}, [%4];" \
                 : "=r"(r0), "=r"(r1), "=r"(r2), "=r"(r3) : "r"(addr))

#define MMA16816(d, a0, a1, a2, a3, b0, b1) \
    asm volatile("mma.sync.aligned.m16n8k16.row.col.f32.f16.f16.f32 " \
                 "{%0,%1,%2,%3}, {%4,%5,%6,%7}, {%8,%9}, {%0,%1,%2,%3};" \
                 : "+f"((d)[0]), "+f"((d)[1]), "+f"((d)[2]), "+f"((d)[3]) \
                 : "r"(a0), "r"(a1), "r"(a2), "r"(a3), "r"(b0), "r"(b1))

__device__ __forceinline__ float softplus100(float v) {
    float y = 100.f * v;
    if (y > 20.f) return v;
    return log1pf(__expf(y)) * 0.01f;
}

// ---------------- weight-norm fold + fp16 round ---------------------------------
__global__ void prep_weights_tc(const float* __restrict__ v, const float* __restrict__ g,
                                int Kdim, int KPAD,
                                __half* __restrict__ W,
                                float* __restrict__ lastrow)
{
    int j = blockIdx.x;
    const float* vr = v + (size_t)j * Kdim;
    __shared__ float red[256];
    float s = 0.f;
    for (int k = threadIdx.x; k < Kdim; k += 256) { float t = vr[k]; s += t * t; }
    red[threadIdx.x] = s;
    __syncthreads();
    for (int st = 128; st > 0; st >>= 1) {
        if (threadIdx.x < st) red[threadIdx.x] += red[threadIdx.x + st];
        __syncthreads();
    }
    float scale = g[j] * rsqrtf(red[0]);
    if (lastrow != nullptr && j == 256) {
        for (int k = threadIdx.x; k < Kdim; k += 256) lastrow[k] = vr[k] * scale;
        return;
    }
    for (int k = threadIdx.x; k < Kdim; k += 256)
        W[(size_t)j * KPAD + k] = __float2half(vr[k] * scale);
}

// ---------------- encode: pos-embed + multires hash grid (fp16 out) -------------
__global__ void encode_kernel(const float* __restrict__ x,
                              const float* __restrict__ tab,
                              __half* __restrict__ F,
                              LevelParams lp)
{
    int i = blockIdx.x * blockDim.x + threadIdx.x;
    if (i >= NPTS) return;
    float px = x[3 * i + 0], py = x[3 * i + 1], pz = x[3 * i + 2];

    float vals[72];
    vals[0] = px; vals[1] = py; vals[2] = pz;
#pragma unroll
    for (int j = 0; j < 6; j++) {
        float f = (float)(1 << j);
        float s0, c0, s1, c1, s2, c2;
        __sincosf(f * px, &s0, &c0);
        __sincosf(f * py, &s1, &c1);
        __sincosf(f * pz, &s2, &c2);
        vals[3 + 6 * j + 0] = s0; vals[3 + 6 * j + 1] = s1; vals[3 + 6 * j + 2] = s2;
        vals[3 + 6 * j + 3] = c0; vals[3 + 6 * j + 4] = c1; vals[3 + 6 * j + 5] = c2;
    }

    float xc = fminf(fmaxf(px, 0.f), 1.f);
    float yc = fminf(fmaxf(py, 0.f), 1.f);
    float zc = fminf(fmaxf(pz, 0.f), 1.f);

    for (int l = 0; l < 16; l++) {
        int   R  = lp.R[l];
        float Rf = (float)R;
        float fx = xc * Rf, fy = yc * Rf, fz = zc * Rf;
        float f0x = floorf(fx), f0y = floorf(fy), f0z = floorf(fz);
        float w1x = fx - f0x, w1y = fy - f0y, w1z = fz - f0z;
        float wx[2] = {1.f - w1x, w1x};
        float wy[2] = {1.f - w1y, w1y};
        float wz[2] = {1.f - w1z, w1z};
        unsigned ux = (unsigned)f0x, uy = (unsigned)f0y, uz = (unsigned)f0z;
        unsigned Ru = (unsigned)R, R1 = Ru + 1u;
        int dns = lp.dense[l];
        const float2* tabL = (const float2*)tab + (size_t)l * TSZ;
        float ax = 0.f, ay = 0.f;
#pragma unroll
        for (int c = 0; c < 8; c++) {
            unsigned ox = c & 1, oy = (c >> 1) & 1, oz = (c >> 2) & 1;
            unsigned ix = min(ux + ox, Ru);
            unsigned iy = min(uy + oy, Ru);
            unsigned iz = min(uz + oz, Ru);
            unsigned flat;
            if (dns) flat = ix + R1 * (iy + R1 * iz);
            else     flat = (ix ^ (iy * P1) ^ (iz * P2)) & (TSZ - 1u);
            float wc = wx[ox] * wy[oy] * wz[oz];
            float2 tv = __ldg(&tabL[flat]);
            ax = fmaf(wc, tv.x, ax);
            ay = fmaf(wc, tv.y, ay);
        }
        vals[39 + 2 * l] = ax;
        vals[40 + 2 * l] = ay;
    }

    // vectorized fp16 store: 9 x uint4 (cols 0..71)
    __half* Fh = F + (size_t)i * KP0;
#pragma unroll
    for (int c0 = 0; c0 < 72; c0 += 8) {
        uint32 w[4];
#pragma unroll
        for (int q = 0; q < 4; q++) {
            __half2 hv = __floats2half2_rn(vals[c0 + 2 * q], vals[c0 + 2 * q + 1]);
            w[q] = *(uint32*)&hv;
        }
        *(uint4*)(Fh + c0) = make_uint4(w[0], w[1], w[2], w[3]);
    }
}

// ---------------- fp16 GEMM via mma.sync (HMMA), fp32 accumulate ----------------
// CTA tile 128(M) x 128(N), 256 threads (8 warps of 32x64), 2-stage cp.async,
// ONE __syncthreads per K-chunk (wait -> sync -> issue -> compute).
#define KC   32
#define RS   80                        // smem row stride bytes (bank-permuting pad)
#define ATB  (128 * RS)                // 10240 bytes per tile array
#define STG  (2 * ATB)                 // A, B per stage (20480)
#define SMEM_SZ (2 * STG)              // 40960

template<int KPAD, bool ACT, bool LAST>
__global__ __launch_bounds__(256, 2)
void gemm_mma(const __half* __restrict__ A, const __half* __restrict__ B,
              const float* __restrict__ bias,
              __half* __restrict__ O, float* __restrict__ Of)
{
    constexpr int NC = KPAD / KC;
    extern __shared__ char smem[];
    uint32 sb = smem_u32(smem);

    const int tid  = threadIdx.x;
    const int lane = tid & 31;
    const int wid  = tid >> 5;
    const int warpM = wid & 3;         // 0..3 -> 32-row slice
    const int warpN = wid >> 2;        // 0..1 -> 64-col slice
    const int mBase = blockIdx.y * 128;
    const int nBase = blockIdx.x * 128;

    // global load mapping: per array 512 x 16B transfers; thread does idx, idx+256
    const int ldRow0 = tid >> 2, ldSlot = tid & 3;
    const int ldRow1 = ldRow0 + 64;

    const char* pA = (const char*)(A + (size_t)mBase * KPAD);
    const char* pB = (const char*)(B + (size_t)nBase * KPAD);

    auto issue_chunk = [&](int c) {
        uint32 stage = sb + (c & 1) * STG;
        size_t gofs0 = (size_t)ldRow0 * (KPAD * 2) + c * (KC * 2) + ldSlot * 16;
        size_t gofs1 = (size_t)ldRow1 * (KPAD * 2) + c * (KC * 2) + ldSlot * 16;
        uint32 sofs0 = ldRow0 * RS + ldSlot * 16;
        uint32 sofs1 = ldRow1 * RS + ldSlot * 16;
        CP_ASYNC16(stage + sofs0,       pA + gofs0);
        CP_ASYNC16(stage + sofs1,       pA + gofs1);
        CP_ASYNC16(stage + ATB + sofs0, pB + gofs0);
        CP_ASYNC16(stage + ATB + sofs1, pB + gofs1);
        CP_COMMIT();
    };

    float acc[2][8][4];
#pragma unroll
    for (int mt = 0; mt < 2; mt++)
#pragma unroll
        for (int nt = 0; nt < 8; nt++)
#pragma unroll
            for (int q = 0; q < 4; q++) acc[mt][nt][q] = 0.f;

    const uint32 aOff = (uint32)(warpM * 32 + (lane & 15)) * RS + (lane >> 4) * 16;
    const uint32 bOff = (uint32)(warpN * 64 + (lane & 7) + ((lane >> 4) << 3)) * RS
                        + ((lane >> 3) & 1) * 16;

    issue_chunk(0);

    for (int c = 0; c < NC; c++) {
        // chunk c is the only group in flight; wait, then the barrier publishes
        // its data AND certifies compute of c-1 finished (buffer (c+1)&1 free).
        CP_WAIT(0);
        __syncthreads();
        if (c + 1 < NC) issue_chunk(c + 1);   // overlaps compute of chunk c

        uint32 stage = sb + (c & 1) * STG;
        uint32 sA = stage + aOff;
        uint32 sB = stage + ATB + bOff;

#pragma unroll
        for (int ks = 0; ks < 2; ks++) {
            uint32 kb = ks * 32;               // 16 k-elems = 32 bytes
            uint32 a[2][4];
            LDSM4(a[0][0], a[0][1], a[0][2], a[0][3], sA + kb);
            LDSM4(a[1][0], a[1][1], a[1][2], a[1][3], sA + 16 * RS + kb);
#pragma unroll
            for (int np = 0; np < 4; np++) {
                uint32 b[4];
                LDSM4(b[0], b[1], b[2], b[3], sB + np * 16 * RS + kb);
#pragma unroll
                for (int mt = 0; mt < 2; mt++) {
                    MMA16816(acc[mt][2 * np + 0], a[mt][0], a[mt][1], a[mt][2], a[mt][3], b[0], b[1]);
                    MMA16816(acc[mt][2 * np + 1], a[mt][0], a[mt][1], a[mt][2], a[mt][3], b[2], b[3]);
                }
            }
        }
    }

    // ---------------- epilogue: bias + act + store ------------------------------
#pragma unroll
    for (int mt = 0; mt < 2; mt++) {
        int m0 = mBase + warpM * 32 + mt * 16 + (lane >> 2);
#pragma unroll
        for (int nt = 0; nt < 8; nt++) {
            int n0 = nBase + warpN * 64 + nt * 8 + (lane & 3) * 2;
            float bj0 = __ldg(bias + n0), bj1 = __ldg(bias + n0 + 1);
#pragma unroll
            for (int half = 0; half < 2; half++) {
                int m = m0 + half * 8;
                float v0 = acc[mt][nt][2 * half + 0] + bj0;
                float v1 = acc[mt][nt][2 * half + 1] + bj1;
                if (ACT) { v0 = softplus100(v0); v1 = softplus100(v1); }
                if (LAST) {
                    float* orow = Of + (size_t)m * 257 + n0;
                    orow[0] = v0; orow[1] = v1;
                } else {
                    __half2 hv = __floats2half2_rn(v0, v1);
                    *(__half2*)(O + (size_t)m * 256 + n0) = hv;
                }
            }
        }
    }
}

// ---------------- last output column (row 256 of v2) ----------------------------
__global__ void lastcol_kernel(const __half* __restrict__ H,
                               const float* __restrict__ wlast,
                               const float* __restrict__ b2,
                               float* __restrict__ out)
{
    __shared__ float w[256];
    int tid = threadIdx.x;
    w[tid] = wlast[tid];
    __syncthreads();
    int lane = tid & 31, warp = tid >> 5;
    size_t i = (size_t)blockIdx.x * 8 + warp;
    const __half* h = H + i * 256;
    float s = 0.f;
#pragma unroll
    for (int q = 0; q < 8; q++) {
        int k = lane + 32 * q;
        s = fmaf(__half2float(h[k]), w[k], s);
    }
#pragma unroll
    for (int off = 16; off > 0; off >>= 1) s += __shfl_xor_sync(0xffffffffu, s, off);
    if (lane == 0) out[i * 257 + 256] = s + b2[256];
}

// ---------------- launch --------------------------------------------------------
extern "C" void kernel_launch(void* const* d_in, const int* in_sizes, int n_in,
                              void* d_out, int out_size)
{
    const float* x      = (const float*)d_in[0];
    const float* tables = (const float*)d_in[1];
    const float* v0 = (const float*)d_in[2];
    const float* g0 = (const float*)d_in[3];
    const float* b0 = (const float*)d_in[4];
    const float* v1 = (const float*)d_in[5];
    const float* g1 = (const float*)d_in[6];
    const float* b1 = (const float*)d_in[7];
    const float* v2 = (const float*)d_in[8];
    const float* g2 = (const float*)d_in[9];
    const float* b2 = (const float*)d_in[10];
    float* out = (float*)d_out;

    __half *F, *H0, *H1, *W0, *W1, *W2;
    float* w2last;
    cudaGetSymbolAddress((void**)&F,  g_F);
    cudaGetSymbolAddress((void**)&H0, g_H0);
    cudaGetSymbolAddress((void**)&H1, g_H1);
    cudaGetSymbolAddress((void**)&W0, g_W0);
    cudaGetSymbolAddress((void**)&W1, g_W1);
    cudaGetSymbolAddress((void**)&W2, g_W2);
    cudaGetSymbolAddress((void**)&w2last, g_w2last);

    LevelParams lp;
    double SCALE = pow(2.0, log2(2048.0 / 16.0) / 15.0);
    for (int l = 0; l < 16; l++) {
        int R = (int)ceil(16.0 * pow(SCALE, (double)l));
        lp.R[l] = R;
        long long cc = (long long)R + 1;
        lp.dense[l] = (cc * cc * cc <= (long long)TSZ) ? 1 : 0;
    }

    cudaFuncSetAttribute(gemm_mma<KP0, true,  false>, cudaFuncAttributeMaxDynamicSharedMemorySize, SMEM_SZ);
    cudaFuncSetAttribute(gemm_mma<256, true,  false>, cudaFuncAttributeMaxDynamicSharedMemorySize, SMEM_SZ);
    cudaFuncSetAttribute(gemm_mma<256, false, true >, cudaFuncAttributeMaxDynamicSharedMemorySize, SMEM_SZ);

    prep_weights_tc<<<256, 256>>>(v0, g0, 71,  KP0, W0, nullptr);
    prep_weights_tc<<<256, 256>>>(v1, g1, 256, 256, W1, nullptr);
    prep_weights_tc<<<257, 256>>>(v2, g2, 256, 256, W2, w2last);

    encode_kernel<<<NPTS / 256, 256>>>(x, tables, F, lp);

    dim3 grid(2, NPTS / 128);
    gemm_mma<KP0, true,  false><<<grid, 256, SMEM_SZ>>>(F,  W0, b0, H0, nullptr);
    gemm_mma<256, true,  false><<<grid, 256, SMEM_SZ>>>(H0, W1, b1, H1, nullptr);
    gemm_mma<256, false, true ><<<grid, 256, SMEM_SZ>>>(H1, W2, b2, nullptr, out);

    lastcol_kernel<<<NPTS / 8, 256>>>(H1, w2last, b2, out);
}

// round 12
// speedup vs baseline: 2.3146x; 1.0202x over previous
#include <cuda_runtime.h>
#include <cuda_fp16.h>
#include <math.h>
#include <stdint.h>

typedef unsigned int uint32;

#define NPTS 524288
#define TSZ  (1u << 19)
#define P1   2654435761u
#define P2   805459861u

#define KP0  96                        // layer-0 K padding (71 real cols)

// ---------------- scratch (device globals; allocation-free rule) ----------------
// Padding regions (cols 71..95 of F, rows k>=71 of W0) are BSS-zero (fp16 +0.0)
// and never written by any kernel, so they stay zero across graph replays.
__device__ __half g_F [(size_t)NPTS * KP0];
__device__ __half g_H0[(size_t)NPTS * 256];
__device__ __half g_H1[(size_t)NPTS * 256];
__device__ __half g_W0[256 * KP0];             // [N=256][Kpad] K-major
__device__ __half g_W1[256 * 256];
__device__ __half g_W2[256 * 256];             // rows 0..255 of v2
__device__ float  g_w2last[256];               // row 256 of v2 (folded)

struct LevelParams { int R[16]; int dense[16]; };

// ---------------- PTX helpers ---------------------------------------------------
__device__ __forceinline__ uint32 smem_u32(const void* p) {
    uint32 a;
    asm("{ .reg .u64 t; cvta.to.shared.u64 t, %1; cvt.u32.u64 %0, t; }" : "=r"(a) : "l"(p));
    return a;
}

#define CP_ASYNC16(dst, src) asm volatile("cp.async.cg.shared.global [%0], [%1], 16;" :: "r"(dst), "l"(src))
#define CP_COMMIT()          asm volatile("cp.async.commit_group;" ::: "memory")
#define CP_WAIT(n)           asm volatile("cp.async.wait_group %0;" :: "n"(n) : "memory")

#define LDSM4(r0, r1, r2, r3, addr) \
    asm volatile("ldmatrix.sync.aligned.m8n8.x4.shared.b16 {%0,%1,%2,%3}, [%4];" \
                 : "=r"(r0), "=r"(r1), "=r"(r2), "=r"(r3) : "r"(addr))

#define MMA16816(d, a0, a1, a2, a3, b0, b1) \
    asm volatile("mma.sync.aligned.m16n8k16.row.col.f32.f16.f16.f32 " \
                 "{%0,%1,%2,%3}, {%4,%5,%6,%7}, {%8,%9}, {%0,%1,%2,%3};" \
                 : "+f"((d)[0]), "+f"((d)[1]), "+f"((d)[2]), "+f"((d)[3]) \
                 : "r"(a0), "r"(a1), "r"(a2), "r"(a3), "r"(b0), "r"(b1))

__device__ __forceinline__ float softplus100(float v) {
    float y = 100.f * v;
    if (y > 20.f) return v;
    return log1pf(__expf(y)) * 0.01f;
}

// ---------------- weight-norm fold + fp16 round ---------------------------------
__global__ void prep_weights_tc(const float* __restrict__ v, const float* __restrict__ g,
                                int Kdim, int KPAD,
                                __half* __restrict__ W,
                                float* __restrict__ lastrow)
{
    int j = blockIdx.x;
    const float* vr = v + (size_t)j * Kdim;
    __shared__ float red[256];
    float s = 0.f;
    for (int k = threadIdx.x; k < Kdim; k += 256) { float t = vr[k]; s += t * t; }
    red[threadIdx.x] = s;
    __syncthreads();
    for (int st = 128; st > 0; st >>= 1) {
        if (threadIdx.x < st) red[threadIdx.x] += red[threadIdx.x + st];
        __syncthreads();
    }
    float scale = g[j] * rsqrtf(red[0]);
    if (lastrow != nullptr && j == 256) {
        for (int k = threadIdx.x; k < Kdim; k += 256) lastrow[k] = vr[k] * scale;
        return;
    }
    for (int k = threadIdx.x; k < Kdim; k += 256)
        W[(size_t)j * KPAD + k] = __float2half(vr[k] * scale);
}

// ---------------- encode: pos-embed + multires hash grid (fp16 out) -------------
__global__ void encode_kernel(const float* __restrict__ x,
                              const float* __restrict__ tab,
                              __half* __restrict__ F,
                              LevelParams lp)
{
    int i = blockIdx.x * blockDim.x + threadIdx.x;
    if (i >= NPTS) return;
    float px = x[3 * i + 0], py = x[3 * i + 1], pz = x[3 * i + 2];

    float vals[72];
    vals[0] = px; vals[1] = py; vals[2] = pz;
#pragma unroll
    for (int j = 0; j < 6; j++) {
        float f = (float)(1 << j);
        float s0, c0, s1, c1, s2, c2;
        __sincosf(f * px, &s0, &c0);
        __sincosf(f * py, &s1, &c1);
        __sincosf(f * pz, &s2, &c2);
        vals[3 + 6 * j + 0] = s0; vals[3 + 6 * j + 1] = s1; vals[3 + 6 * j + 2] = s2;
        vals[3 + 6 * j + 3] = c0; vals[3 + 6 * j + 4] = c1; vals[3 + 6 * j + 5] = c2;
    }

    float xc = fminf(fmaxf(px, 0.f), 1.f);
    float yc = fminf(fmaxf(py, 0.f), 1.f);
    float zc = fminf(fmaxf(pz, 0.f), 1.f);

    for (int l = 0; l < 16; l++) {
        int   R  = lp.R[l];
        float Rf = (float)R;
        float fx = xc * Rf, fy = yc * Rf, fz = zc * Rf;
        float f0x = floorf(fx), f0y = floorf(fy), f0z = floorf(fz);
        float w1x = fx - f0x, w1y = fy - f0y, w1z = fz - f0z;
        float wx[2] = {1.f - w1x, w1x};
        float wy[2] = {1.f - w1y, w1y};
        float wz[2] = {1.f - w1z, w1z};
        unsigned ux = (unsigned)f0x, uy = (unsigned)f0y, uz = (unsigned)f0z;
        unsigned Ru = (unsigned)R, R1 = Ru + 1u;
        int dns = lp.dense[l];
        const float2* tabL = (const float2*)tab + (size_t)l * TSZ;
        float ax = 0.f, ay = 0.f;
#pragma unroll
        for (int c = 0; c < 8; c++) {
            unsigned ox = c & 1, oy = (c >> 1) & 1, oz = (c >> 2) & 1;
            unsigned ix = min(ux + ox, Ru);
            unsigned iy = min(uy + oy, Ru);
            unsigned iz = min(uz + oz, Ru);
            unsigned flat;
            if (dns) flat = ix + R1 * (iy + R1 * iz);
            else     flat = (ix ^ (iy * P1) ^ (iz * P2)) & (TSZ - 1u);
            float wc = wx[ox] * wy[oy] * wz[oz];
            float2 tv = __ldg(&tabL[flat]);
            ax = fmaf(wc, tv.x, ax);
            ay = fmaf(wc, tv.y, ay);
        }
        vals[39 + 2 * l] = ax;
        vals[40 + 2 * l] = ay;
    }

    // vectorized fp16 store: 9 x uint4 (cols 0..71)
    __half* Fh = F + (size_t)i * KP0;
#pragma unroll
    for (int c0 = 0; c0 < 72; c0 += 8) {
        uint32 w[4];
#pragma unroll
        for (int q = 0; q < 4; q++) {
            __half2 hv = __floats2half2_rn(vals[c0 + 2 * q], vals[c0 + 2 * q + 1]);
            w[q] = *(uint32*)&hv;
        }
        *(uint4*)(Fh + c0) = make_uint4(w[0], w[1], w[2], w[3]);
    }
}

// ---------------- fp16 GEMM via mma.sync (HMMA), fp32 accumulate ----------------
// CTA tile 64(M) x 256(N full) -> A read ONCE per layer. 256 threads,
// 8 warps of 32x64 (warpM 0..1, warpN 0..3). 3-stage cp.async pipeline,
// ONE __syncthreads per K-chunk (wait(1) -> sync -> issue(c+2) -> compute(c)).
#define KC   32
#define RS   80                        // smem row stride bytes (bank-permuting pad)
#define ATA  (64 * RS)                 // A tile array bytes  (5120)
#define ATB  (256 * RS)                // B tile array bytes  (20480)
#define STG  (ATA + ATB)               // per stage (25600)
#define NSTAGE 3
#define SMEM_SZ (NSTAGE * STG)         // 76800 -> 2 CTAs/SM

template<int KPAD, bool ACT, bool LAST>
__global__ __launch_bounds__(256, 2)
void gemm_mma(const __half* __restrict__ A, const __half* __restrict__ B,
              const float* __restrict__ bias,
              __half* __restrict__ O, float* __restrict__ Of)
{
    constexpr int NC = KPAD / KC;
    extern __shared__ char smem[];
    uint32 sb = smem_u32(smem);

    const int tid  = threadIdx.x;
    const int lane = tid & 31;
    const int wid  = tid >> 5;
    const int warpM = wid & 1;         // 0..1 -> 32-row slice
    const int warpN = wid >> 1;        // 0..3 -> 64-col slice
    const int mBase = blockIdx.x * 64;

    // global load mapping (16B chunks, KC=32 -> 4 slots/row):
    //   A: 64 rows x 4 = 256 -> 1 per thread
    //   B: 256 rows x 4 = 1024 -> 4 per thread
    const int ldRow = tid >> 2, ldSlot = tid & 3;

    const char* pA = (const char*)(A + (size_t)mBase * KPAD);
    const char* pB = (const char*)B;

    auto issue_chunk = [&](int c) {
        uint32 stage = sb + (c % NSTAGE) * STG;
        size_t ga = (size_t)ldRow * (KPAD * 2) + c * (KC * 2) + ldSlot * 16;
        uint32 sa = ldRow * RS + ldSlot * 16;
        CP_ASYNC16(stage + sa, pA + ga);
#pragma unroll
        for (int t = 0; t < 4; t++) {
            int row = ldRow + t * 64;
            size_t gb = (size_t)row * (KPAD * 2) + c * (KC * 2) + ldSlot * 16;
            uint32 sbo = row * RS + ldSlot * 16;
            CP_ASYNC16(stage + ATA + sbo, pB + gb);
        }
        CP_COMMIT();
    };

    float acc[2][8][4];
#pragma unroll
    for (int mt = 0; mt < 2; mt++)
#pragma unroll
        for (int nt = 0; nt < 8; nt++)
#pragma unroll
            for (int q = 0; q < 4; q++) acc[mt][nt][q] = 0.f;

    const uint32 aOff = (uint32)(warpM * 32 + (lane & 15)) * RS + (lane >> 4) * 16;
    const uint32 bOff = (uint32)(warpN * 64 + (lane & 7) + ((lane >> 4) << 3)) * RS
                        + ((lane >> 3) & 1) * 16;

    issue_chunk(0);
    if (NC > 1) issue_chunk(1);

    for (int c = 0; c < NC; c++) {
        // wait for chunk c (allow c+1 to stay in flight); the barrier publishes
        // c's smem data AND certifies compute of c-1 finished, so buffer
        // (c+2)%3 == (c-1)%3 is free for the next issue.
        if (c + 1 < NC) { CP_WAIT(1); } else { CP_WAIT(0); }
        __syncthreads();
        if (c + 2 < NC) issue_chunk(c + 2);   // overlaps compute of chunk c

        uint32 stage = sb + (c % NSTAGE) * STG;
        uint32 sA = stage + aOff;
        uint32 sB = stage + ATA + bOff;

#pragma unroll
        for (int ks = 0; ks < 2; ks++) {
            uint32 kb = ks * 32;               // 16 k-elems = 32 bytes
            uint32 a[2][4];
            LDSM4(a[0][0], a[0][1], a[0][2], a[0][3], sA + kb);
            LDSM4(a[1][0], a[1][1], a[1][2], a[1][3], sA + 16 * RS + kb);
#pragma unroll
            for (int np = 0; np < 4; np++) {
                uint32 b[4];
                LDSM4(b[0], b[1], b[2], b[3], sB + np * 16 * RS + kb);
#pragma unroll
                for (int mt = 0; mt < 2; mt++) {
                    MMA16816(acc[mt][2 * np + 0], a[mt][0], a[mt][1], a[mt][2], a[mt][3], b[0], b[1]);
                    MMA16816(acc[mt][2 * np + 1], a[mt][0], a[mt][1], a[mt][2], a[mt][3], b[2], b[3]);
                }
            }
        }
    }

    // ---------------- epilogue: bias + act + store ------------------------------
#pragma unroll
    for (int mt = 0; mt < 2; mt++) {
        int m0 = mBase + warpM * 32 + mt * 16 + (lane >> 2);
#pragma unroll
        for (int nt = 0; nt < 8; nt++) {
            int n0 = warpN * 64 + nt * 8 + (lane & 3) * 2;
            float bj0 = __ldg(bias + n0), bj1 = __ldg(bias + n0 + 1);
#pragma unroll
            for (int half = 0; half < 2; half++) {
                int m = m0 + half * 8;
                float v0 = acc[mt][nt][2 * half + 0] + bj0;
                float v1 = acc[mt][nt][2 * half + 1] + bj1;
                if (ACT) { v0 = softplus100(v0); v1 = softplus100(v1); }
                if (LAST) {
                    float* orow = Of + (size_t)m * 257 + n0;
                    orow[0] = v0; orow[1] = v1;
                } else {
                    __half2 hv = __floats2half2_rn(v0, v1);
                    *(__half2*)(O + (size_t)m * 256 + n0) = hv;
                }
            }
        }
    }
}

// ---------------- last output column (row 256 of v2) ----------------------------
__global__ void lastcol_kernel(const __half* __restrict__ H,
                               const float* __restrict__ wlast,
                               const float* __restrict__ b2,
                               float* __restrict__ out)
{
    __shared__ float w[256];
    int tid = threadIdx.x;
    w[tid] = wlast[tid];
    __syncthreads();
    int lane = tid & 31, warp = tid >> 5;
    size_t i = (size_t)blockIdx.x * 8 + warp;
    const __half* h = H + i * 256;
    float s = 0.f;
#pragma unroll
    for (int q = 0; q < 8; q++) {
        int k = lane + 32 * q;
        s = fmaf(__half2float(h[k]), w[k], s);
    }
#pragma unroll
    for (int off = 16; off > 0; off >>= 1) s += __shfl_xor_sync(0xffffffffu, s, off);
    if (lane == 0) out[i * 257 + 256] = s + b2[256];
}

// ---------------- launch --------------------------------------------------------
extern "C" void kernel_launch(void* const* d_in, const int* in_sizes, int n_in,
                              void* d_out, int out_size)
{
    const float* x      = (const float*)d_in[0];
    const float* tables = (const float*)d_in[1];
    const float* v0 = (const float*)d_in[2];
    const float* g0 = (const float*)d_in[3];
    const float* b0 = (const float*)d_in[4];
    const float* v1 = (const float*)d_in[5];
    const float* g1 = (const float*)d_in[6];
    const float* b1 = (const float*)d_in[7];
    const float* v2 = (const float*)d_in[8];
    const float* g2 = (const float*)d_in[9];
    const float* b2 = (const float*)d_in[10];
    float* out = (float*)d_out;

    __half *F, *H0, *H1, *W0, *W1, *W2;
    float* w2last;
    cudaGetSymbolAddress((void**)&F,  g_F);
    cudaGetSymbolAddress((void**)&H0, g_H0);
    cudaGetSymbolAddress((void**)&H1, g_H1);
    cudaGetSymbolAddress((void**)&W0, g_W0);
    cudaGetSymbolAddress((void**)&W1, g_W1);
    cudaGetSymbolAddress((void**)&W2, g_W2);
    cudaGetSymbolAddress((void**)&w2last, g_w2last);

    LevelParams lp;
    double SCALE = pow(2.0, log2(2048.0 / 16.0) / 15.0);
    for (int l = 0; l < 16; l++) {
        int R = (int)ceil(16.0 * pow(SCALE, (double)l));
        lp.R[l] = R;
        long long cc = (long long)R + 1;
        lp.dense[l] = (cc * cc * cc <= (long long)TSZ) ? 1 : 0;
    }

    cudaFuncSetAttribute(gemm_mma<KP0, true,  false>, cudaFuncAttributeMaxDynamicSharedMemorySize, SMEM_SZ);
    cudaFuncSetAttribute(gemm_mma<256, true,  false>, cudaFuncAttributeMaxDynamicSharedMemorySize, SMEM_SZ);
    cudaFuncSetAttribute(gemm_mma<256, false, true >, cudaFuncAttributeMaxDynamicSharedMemorySize, SMEM_SZ);

    prep_weights_tc<<<256, 256>>>(v0, g0, 71,  KP0, W0, nullptr);
    prep_weights_tc<<<256, 256>>>(v1, g1, 256, 256, W1, nullptr);
    prep_weights_tc<<<257, 256>>>(v2, g2, 256, 256, W2, w2last);

    encode_kernel<<<NPTS / 256, 256>>>(x, tables, F, lp);

    gemm_mma<KP0, true,  false><<<NPTS / 64, 256, SMEM_SZ>>>(F,  W0, b0, H0, nullptr);
    gemm_mma<256, true,  false><<<NPTS / 64, 256, SMEM_SZ>>>(H0, W1, b1, H1, nullptr);
    gemm_mma<256, false, true ><<<NPTS / 64, 256, SMEM_SZ>>>(H1, W2, b2, nullptr, out);

    lastcol_kernel<<<NPTS / 8, 256>>>(H1, w2last, b2, out);
}

// round 13
// speedup vs baseline: 2.4648x; 1.0649x over previous
#include <cuda_runtime.h>
#include <cuda_fp16.h>
#include <math.h>
#include <stdint.h>

typedef unsigned int uint32;

#define NPTS 524288
#define TSZ  (1u << 19)
#define P1   2654435761u
#define P2   805459861u

#define KP0  96                        // layer-0 K padding (71 real cols)

// ---------------- scratch (device globals; allocation-free rule) ----------------
// Padding regions (cols 71..95 of F, rows k>=71 of W0) are BSS-zero (fp16 +0.0)
// and never written by any kernel, so they stay zero across graph replays.
__device__ __half g_F [(size_t)NPTS * KP0];
__device__ __half g_H0[(size_t)NPTS * 256];
__device__ __half g_H1[(size_t)NPTS * 256];
__device__ __half g_W0[256 * KP0];             // [N=256][Kpad] K-major
__device__ __half g_W1[256 * 256];
__device__ __half g_W2[256 * 256];             // rows 0..255 of v2
__device__ float  g_w2last[256];               // row 256 of v2 (folded)

struct LevelParams { int R[16]; int dense[16]; };

// ---------------- PTX helpers ---------------------------------------------------
__device__ __forceinline__ uint32 smem_u32(const void* p) {
    uint32 a;
    asm("{ .reg .u64 t; cvta.to.shared.u64 t, %1; cvt.u32.u64 %0, t; }" : "=r"(a) : "l"(p));
    return a;
}

#define CP_ASYNC16(dst, src) asm volatile("cp.async.cg.shared.global [%0], [%1], 16;" :: "r"(dst), "l"(src))
#define CP_COMMIT()          asm volatile("cp.async.commit_group;" ::: "memory")
#define CP_WAIT(n)           asm volatile("cp.async.wait_group %0;" :: "n"(n) : "memory")

#define LDSM4(r0, r1, r2, r3, addr) \
    asm volatile("ldmatrix.sync.aligned.m8n8.x4.shared.b16 {%0,%1,%2,%3}, [%4];" \
                 : "=r"(r0), "=r"(r1), "=r"(r2), "=r"(r3) : "r"(addr))

#define MMA16816(d, a0, a1, a2, a3, b0, b1) \
    asm volatile("mma.sync.aligned.m16n8k16.row.col.f32.f16.f16.f32 " \
                 "{%0,%1,%2,%3}, {%4,%5,%6,%7}, {%8,%9}, {%0,%1,%2,%3};" \
                 : "+f"((d)[0]), "+f"((d)[1]), "+f"((d)[2]), "+f"((d)[3]) \
                 : "r"(a0), "r"(a1), "r"(a2), "r"(a3), "r"(b0), "r"(b1))

__device__ __forceinline__ float softplus100(float v) {
    float y = 100.f * v;
    if (y > 20.f) return v;
    return log1pf(__expf(y)) * 0.01f;
}

// ---------------- weight-norm fold + fp16 round ---------------------------------
__global__ void prep_weights_tc(const float* __restrict__ v, const float* __restrict__ g,
                                int Kdim, int KPAD,
                                __half* __restrict__ W,
                                float* __restrict__ lastrow)
{
    int j = blockIdx.x;
    const float* vr = v + (size_t)j * Kdim;
    __shared__ float red[256];
    float s = 0.f;
    for (int k = threadIdx.x; k < Kdim; k += 256) { float t = vr[k]; s += t * t; }
    red[threadIdx.x] = s;
    __syncthreads();
    for (int st = 128; st > 0; st >>= 1) {
        if (threadIdx.x < st) red[threadIdx.x] += red[threadIdx.x + st];
        __syncthreads();
    }
    float scale = g[j] * rsqrtf(red[0]);
    if (lastrow != nullptr && j == 256) {
        for (int k = threadIdx.x; k < Kdim; k += 256) lastrow[k] = vr[k] * scale;
        return;
    }
    for (int k = threadIdx.x; k < Kdim; k += 256)
        W[(size_t)j * KPAD + k] = __float2half(vr[k] * scale);
}

// ---------------- encode: pos-embed + multires hash grid (fp16 out) -------------
// Level loop fully unrolled so vals[] is register-resident (no local-mem spills).
__global__ void encode_kernel(const float* __restrict__ x,
                              const float* __restrict__ tab,
                              __half* __restrict__ F,
                              LevelParams lp)
{
    int i = blockIdx.x * blockDim.x + threadIdx.x;
    if (i >= NPTS) return;
    float px = x[3 * i + 0], py = x[3 * i + 1], pz = x[3 * i + 2];

    float vals[72];
    vals[0] = px; vals[1] = py; vals[2] = pz;
#pragma unroll
    for (int j = 0; j < 6; j++) {
        float f = (float)(1 << j);
        float s0, c0, s1, c1, s2, c2;
        __sincosf(f * px, &s0, &c0);
        __sincosf(f * py, &s1, &c1);
        __sincosf(f * pz, &s2, &c2);
        vals[3 + 6 * j + 0] = s0; vals[3 + 6 * j + 1] = s1; vals[3 + 6 * j + 2] = s2;
        vals[3 + 6 * j + 3] = c0; vals[3 + 6 * j + 4] = c1; vals[3 + 6 * j + 5] = c2;
    }

    float xc = fminf(fmaxf(px, 0.f), 1.f);
    float yc = fminf(fmaxf(py, 0.f), 1.f);
    float zc = fminf(fmaxf(pz, 0.f), 1.f);

#pragma unroll
    for (int l = 0; l < 16; l++) {
        int   R  = lp.R[l];
        float Rf = (float)R;
        float fx = xc * Rf, fy = yc * Rf, fz = zc * Rf;
        float f0x = floorf(fx), f0y = floorf(fy), f0z = floorf(fz);
        float w1x = fx - f0x, w1y = fy - f0y, w1z = fz - f0z;
        float wx[2] = {1.f - w1x, w1x};
        float wy[2] = {1.f - w1y, w1y};
        float wz[2] = {1.f - w1z, w1z};
        unsigned ux = (unsigned)f0x, uy = (unsigned)f0y, uz = (unsigned)f0z;
        unsigned Ru = (unsigned)R, R1 = Ru + 1u;
        int dns = lp.dense[l];
        const float2* tabL = (const float2*)tab + (size_t)l * TSZ;
        float ax = 0.f, ay = 0.f;
#pragma unroll
        for (int c = 0; c < 8; c++) {
            unsigned ox = c & 1, oy = (c >> 1) & 1, oz = (c >> 2) & 1;
            unsigned ix = min(ux + ox, Ru);
            unsigned iy = min(uy + oy, Ru);
            unsigned iz = min(uz + oz, Ru);
            unsigned flat;
            if (dns) flat = ix + R1 * (iy + R1 * iz);
            else     flat = (ix ^ (iy * P1) ^ (iz * P2)) & (TSZ - 1u);
            float wc = wx[ox] * wy[oy] * wz[oz];
            float2 tv = __ldg(&tabL[flat]);
            ax = fmaf(wc, tv.x, ax);
            ay = fmaf(wc, tv.y, ay);
        }
        vals[39 + 2 * l] = ax;
        vals[40 + 2 * l] = ay;
    }

    // vectorized fp16 store: 9 x uint4 (cols 0..71)
    __half* Fh = F + (size_t)i * KP0;
#pragma unroll
    for (int c0 = 0; c0 < 72; c0 += 8) {
        uint32 w[4];
#pragma unroll
        for (int q = 0; q < 4; q++) {
            __half2 hv = __floats2half2_rn(vals[c0 + 2 * q], vals[c0 + 2 * q + 1]);
            w[q] = *(uint32*)&hv;
        }
        *(uint4*)(Fh + c0) = make_uint4(w[0], w[1], w[2], w[3]);
    }
}

// ---------------- fp16 GEMM via mma.sync (HMMA), fp32 accumulate ----------------
// CTA tile 64(M) x 256(N full). 256 threads, 8 warps of 32x64. 3-stage cp.async,
// one __syncthreads per K-chunk. LAST variant also fuses the 257th output column
// (dot(H1_row, w2last)) by re-reading the staged A tile from smem.
#define KC   32
#define RS   80                        // smem row stride bytes (bank-permuting pad)
#define ATA  (64 * RS)                 // A tile array bytes  (5120)
#define ATB  (256 * RS)                // B tile array bytes  (20480)
#define STG  (ATA + ATB)               // per stage (25600)
#define NSTAGE 3
#define SMEM_SZ (NSTAGE * STG)         // 76800 -> 2 CTAs/SM

template<int KPAD, bool ACT, bool LAST>
__global__ __launch_bounds__(256, 2)
void gemm_mma(const __half* __restrict__ A, const __half* __restrict__ B,
              const float* __restrict__ bias,
              const float* __restrict__ wlast,
              __half* __restrict__ O, float* __restrict__ Of)
{
    constexpr int NC = KPAD / KC;
    extern __shared__ char smem[];
    uint32 sb = smem_u32(smem);

    const int tid  = threadIdx.x;
    const int lane = tid & 31;
    const int wid  = tid >> 5;
    const int warpM = wid & 1;         // 0..1 -> 32-row slice
    const int warpN = wid >> 1;        // 0..3 -> 64-col slice
    const int mBase = blockIdx.x * 64;

    // global load mapping (16B chunks, KC=32 -> 4 slots/row):
    //   A: 64 rows x 4 = 256 -> 1 per thread; B: 256 rows x 4 = 1024 -> 4/thread
    const int ldRow = tid >> 2, ldSlot = tid & 3;

    const char* pA = (const char*)(A + (size_t)mBase * KPAD);
    const char* pB = (const char*)B;

    auto issue_chunk = [&](int c) {
        uint32 stage = sb + (c % NSTAGE) * STG;
        size_t ga = (size_t)ldRow * (KPAD * 2) + c * (KC * 2) + ldSlot * 16;
        uint32 sa = ldRow * RS + ldSlot * 16;
        CP_ASYNC16(stage + sa, pA + ga);
#pragma unroll
        for (int t = 0; t < 4; t++) {
            int row = ldRow + t * 64;
            size_t gb = (size_t)row * (KPAD * 2) + c * (KC * 2) + ldSlot * 16;
            uint32 sbo = row * RS + ldSlot * 16;
            CP_ASYNC16(stage + ATA + sbo, pB + gb);
        }
        CP_COMMIT();
    };

    float acc[2][8][4];
#pragma unroll
    for (int mt = 0; mt < 2; mt++)
#pragma unroll
        for (int nt = 0; nt < 8; nt++)
#pragma unroll
            for (int q = 0; q < 4; q++) acc[mt][nt][q] = 0.f;

    float accLast = 0.f;               // fused 257th-column dot (LAST only)

    const uint32 aOff = (uint32)(warpM * 32 + (lane & 15)) * RS + (lane >> 4) * 16;
    const uint32 bOff = (uint32)(warpN * 64 + (lane & 7) + ((lane >> 4) << 3)) * RS
                        + ((lane >> 3) & 1) * 16;

    issue_chunk(0);
    if (NC > 1) issue_chunk(1);

    for (int c = 0; c < NC; c++) {
        // wait for chunk c (c+1 may stay in flight); barrier publishes c's data
        // and certifies compute of c-1 done -> buffer (c+2)%3 free to refill.
        if (c + 1 < NC) { CP_WAIT(1); } else { CP_WAIT(0); }
        __syncthreads();
        if (c + 2 < NC) issue_chunk(c + 2);   // overlaps compute of chunk c

        uint32 stage = sb + (c % NSTAGE) * STG;
        uint32 sA = stage + aOff;
        uint32 sB = stage + ATA + bOff;

        if (LAST) {
            // re-read this thread's own staged A chunk (row ldRow, 8 fp16)
            uint32 aAddr = stage + ldRow * RS + ldSlot * 16;
            uint32 av0, av1, av2, av3;
            asm volatile("ld.shared.v4.u32 {%0,%1,%2,%3}, [%4];"
                         : "=r"(av0), "=r"(av1), "=r"(av2), "=r"(av3) : "r"(aAddr));
            const float* wsp = wlast + c * KC + ldSlot * 8;
            uint32 avw[4] = {av0, av1, av2, av3};
#pragma unroll
            for (int j = 0; j < 4; j++) {
                __half2 h = *(__half2*)&avw[j];
                float2 f = __half22float2(h);
                accLast = fmaf(f.x, __ldg(wsp + 2 * j),     accLast);
                accLast = fmaf(f.y, __ldg(wsp + 2 * j + 1), accLast);
            }
        }

#pragma unroll
        for (int ks = 0; ks < 2; ks++) {
            uint32 kb = ks * 32;               // 16 k-elems = 32 bytes
            uint32 a[2][4];
            LDSM4(a[0][0], a[0][1], a[0][2], a[0][3], sA + kb);
            LDSM4(a[1][0], a[1][1], a[1][2], a[1][3], sA + 16 * RS + kb);
#pragma unroll
            for (int np = 0; np < 4; np++) {
                uint32 b[4];
                LDSM4(b[0], b[1], b[2], b[3], sB + np * 16 * RS + kb);
#pragma unroll
                for (int mt = 0; mt < 2; mt++) {
                    MMA16816(acc[mt][2 * np + 0], a[mt][0], a[mt][1], a[mt][2], a[mt][3], b[0], b[1]);
                    MMA16816(acc[mt][2 * np + 1], a[mt][0], a[mt][1], a[mt][2], a[mt][3], b[2], b[3]);
                }
            }
        }
    }

    // ---------------- fused last column: reduce across the 4 slot-threads -------
    if (LAST) {
        accLast += __shfl_xor_sync(0xffffffffu, accLast, 1);
        accLast += __shfl_xor_sync(0xffffffffu, accLast, 2);
        if (ldSlot == 0)
            Of[(size_t)(mBase + ldRow) * 257 + 256] = accLast + __ldg(bias + 256);
    }

    // ---------------- epilogue: bias + act + store ------------------------------
#pragma unroll
    for (int mt = 0; mt < 2; mt++) {
        int m0 = mBase + warpM * 32 + mt * 16 + (lane >> 2);
#pragma unroll
        for (int nt = 0; nt < 8; nt++) {
            int n0 = warpN * 64 + nt * 8 + (lane & 3) * 2;
            float bj0 = __ldg(bias + n0), bj1 = __ldg(bias + n0 + 1);
#pragma unroll
            for (int half = 0; half < 2; half++) {
                int m = m0 + half * 8;
                float v0 = acc[mt][nt][2 * half + 0] + bj0;
                float v1 = acc[mt][nt][2 * half + 1] + bj1;
                if (ACT) { v0 = softplus100(v0); v1 = softplus100(v1); }
                if (LAST) {
                    float* orow = Of + (size_t)m * 257 + n0;
                    orow[0] = v0; orow[1] = v1;
                } else {
                    __half2 hv = __floats2half2_rn(v0, v1);
                    *(__half2*)(O + (size_t)m * 256 + n0) = hv;
                }
            }
        }
    }
}

// ---------------- launch --------------------------------------------------------
extern "C" void kernel_launch(void* const* d_in, const int* in_sizes, int n_in,
                              void* d_out, int out_size)
{
    const float* x      = (const float*)d_in[0];
    const float* tables = (const float*)d_in[1];
    const float* v0 = (const float*)d_in[2];
    const float* g0 = (const float*)d_in[3];
    const float* b0 = (const float*)d_in[4];
    const float* v1 = (const float*)d_in[5];
    const float* g1 = (const float*)d_in[6];
    const float* b1 = (const float*)d_in[7];
    const float* v2 = (const float*)d_in[8];
    const float* g2 = (const float*)d_in[9];
    const float* b2 = (const float*)d_in[10];
    float* out = (float*)d_out;

    __half *F, *H0, *H1, *W0, *W1, *W2;
    float* w2last;
    cudaGetSymbolAddress((void**)&F,  g_F);
    cudaGetSymbolAddress((void**)&H0, g_H0);
    cudaGetSymbolAddress((void**)&H1, g_H1);
    cudaGetSymbolAddress((void**)&W0, g_W0);
    cudaGetSymbolAddress((void**)&W1, g_W1);
    cudaGetSymbolAddress((void**)&W2, g_W2);
    cudaGetSymbolAddress((void**)&w2last, g_w2last);

    LevelParams lp;
    double SCALE = pow(2.0, log2(2048.0 / 16.0) / 15.0);
    for (int l = 0; l < 16; l++) {
        int R = (int)ceil(16.0 * pow(SCALE, (double)l));
        lp.R[l] = R;
        long long cc = (long long)R + 1;
        lp.dense[l] = (cc * cc * cc <= (long long)TSZ) ? 1 : 0;
    }

    cudaFuncSetAttribute(gemm_mma<KP0, true,  false>, cudaFuncAttributeMaxDynamicSharedMemorySize, SMEM_SZ);
    cudaFuncSetAttribute(gemm_mma<256, true,  false>, cudaFuncAttributeMaxDynamicSharedMemorySize, SMEM_SZ);
    cudaFuncSetAttribute(gemm_mma<256, false, true >, cudaFuncAttributeMaxDynamicSharedMemorySize, SMEM_SZ);

    prep_weights_tc<<<256, 256>>>(v0, g0, 71,  KP0, W0, nullptr);
    prep_weights_tc<<<256, 256>>>(v1, g1, 256, 256, W1, nullptr);
    prep_weights_tc<<<257, 256>>>(v2, g2, 256, 256, W2, w2last);

    encode_kernel<<<NPTS / 256, 256>>>(x, tables, F, lp);

    gemm_mma<KP0, true,  false><<<NPTS / 64, 256, SMEM_SZ>>>(F,  W0, b0, nullptr, H0, nullptr);
    gemm_mma<256, true,  false><<<NPTS / 64, 256, SMEM_SZ>>>(H0, W1, b1, nullptr, H1, nullptr);
    gemm_mma<256, false, true ><<<NPTS / 64, 256, SMEM_SZ>>>(H1, W2, b2, w2last, nullptr, out);
}

// round 14
// speedup vs baseline: 2.5167x; 1.0211x over previous
#include <cuda_runtime.h>
#include <cuda_fp16.h>
#include <math.h>
#include <stdint.h>

typedef unsigned int uint32;

#define NPTS 524288
#define TSZ  (1u << 19)
#define P1   2654435761u
#define P2   805459861u

#define KP0  128                       // layer-0 K padding (71 real cols)

// ---------------- scratch (device globals; allocation-free rule) ----------------
// Padding regions (cols 71..127 of F, rows k>=71 of W0) are BSS-zero (fp16 +0.0)
// and never written by any kernel, so they stay zero across graph replays.
__device__ __half g_F [(size_t)NPTS * KP0];
__device__ __half g_H0[(size_t)NPTS * 256];
__device__ __half g_H1[(size_t)NPTS * 256];
__device__ __half g_W0[256 * KP0];             // [N=256][Kpad] K-major
__device__ __half g_W1[256 * 256];
__device__ __half g_W2[256 * 256];             // rows 0..255 of v2
__device__ float  g_w2last[256];               // row 256 of v2 (folded)

struct LevelParams { int R[16]; int dense[16]; };

// ---------------- PTX helpers ---------------------------------------------------
__device__ __forceinline__ uint32 smem_u32(const void* p) {
    uint32 a;
    asm("{ .reg .u64 t; cvta.to.shared.u64 t, %1; cvt.u32.u64 %0, t; }" : "=r"(a) : "l"(p));
    return a;
}

#define CP_ASYNC16(dst, src) asm volatile("cp.async.cg.shared.global [%0], [%1], 16;" :: "r"(dst), "l"(src))
#define CP_COMMIT()          asm volatile("cp.async.commit_group;" ::: "memory")
#define CP_WAIT(n)           asm volatile("cp.async.wait_group %0;" :: "n"(n) : "memory")

#define LDSM4(r0, r1, r2, r3, addr) \
    asm volatile("ldmatrix.sync.aligned.m8n8.x4.shared.b16 {%0,%1,%2,%3}, [%4];" \
                 : "=r"(r0), "=r"(r1), "=r"(r2), "=r"(r3) : "r"(addr))

#define MMA16816(d, a0, a1, a2, a3, b0, b1) \
    asm volatile("mma.sync.aligned.m16n8k16.row.col.f32.f16.f16.f32 " \
                 "{%0,%1,%2,%3}, {%4,%5,%6,%7}, {%8,%9}, {%0,%1,%2,%3};" \
                 : "+f"((d)[0]), "+f"((d)[1]), "+f"((d)[2]), "+f"((d)[3]) \
                 : "r"(a0), "r"(a1), "r"(a2), "r"(a3), "r"(b0), "r"(b1))

__device__ __forceinline__ float softplus100(float v) {
    float y = 100.f * v;
    if (y > 20.f) return v;
    return log1pf(__expf(y)) * 0.01f;
}

// ---------------- weight-norm fold + fp16 round ---------------------------------
__global__ void prep_weights_tc(const float* __restrict__ v, const float* __restrict__ g,
                                int Kdim, int KPAD,
                                __half* __restrict__ W,
                                float* __restrict__ lastrow)
{
    int j = blockIdx.x;
    const float* vr = v + (size_t)j * Kdim;
    __shared__ float red[256];
    float s = 0.f;
    for (int k = threadIdx.x; k < Kdim; k += 256) { float t = vr[k]; s += t * t; }
    red[threadIdx.x] = s;
    __syncthreads();
    for (int st = 128; st > 0; st >>= 1) {
        if (threadIdx.x < st) red[threadIdx.x] += red[threadIdx.x + st];
        __syncthreads();
    }
    float scale = g[j] * rsqrtf(red[0]);
    if (lastrow != nullptr && j == 256) {
        for (int k = threadIdx.x; k < Kdim; k += 256) lastrow[k] = vr[k] * scale;
        return;
    }
    for (int k = threadIdx.x; k < Kdim; k += 256)
        W[(size_t)j * KPAD + k] = __float2half(vr[k] * scale);
}

// ---------------- encode: pos-embed + multires hash grid (fp16 out) -------------
// Level loop fully unrolled so vals[] is register-resident (no local-mem spills).
__global__ void encode_kernel(const float* __restrict__ x,
                              const float* __restrict__ tab,
                              __half* __restrict__ F,
                              LevelParams lp)
{
    int i = blockIdx.x * blockDim.x + threadIdx.x;
    if (i >= NPTS) return;
    float px = x[3 * i + 0], py = x[3 * i + 1], pz = x[3 * i + 2];

    float vals[72];
    vals[0] = px; vals[1] = py; vals[2] = pz;
#pragma unroll
    for (int j = 0; j < 6; j++) {
        float f = (float)(1 << j);
        float s0, c0, s1, c1, s2, c2;
        __sincosf(f * px, &s0, &c0);
        __sincosf(f * py, &s1, &c1);
        __sincosf(f * pz, &s2, &c2);
        vals[3 + 6 * j + 0] = s0; vals[3 + 6 * j + 1] = s1; vals[3 + 6 * j + 2] = s2;
        vals[3 + 6 * j + 3] = c0; vals[3 + 6 * j + 4] = c1; vals[3 + 6 * j + 5] = c2;
    }

    float xc = fminf(fmaxf(px, 0.f), 1.f);
    float yc = fminf(fmaxf(py, 0.f), 1.f);
    float zc = fminf(fmaxf(pz, 0.f), 1.f);

#pragma unroll
    for (int l = 0; l < 16; l++) {
        int   R  = lp.R[l];
        float Rf = (float)R;
        float fx = xc * Rf, fy = yc * Rf, fz = zc * Rf;
        float f0x = floorf(fx), f0y = floorf(fy), f0z = floorf(fz);
        float w1x = fx - f0x, w1y = fy - f0y, w1z = fz - f0z;
        float wx[2] = {1.f - w1x, w1x};
        float wy[2] = {1.f - w1y, w1y};
        float wz[2] = {1.f - w1z, w1z};
        unsigned ux = (unsigned)f0x, uy = (unsigned)f0y, uz = (unsigned)f0z;
        unsigned Ru = (unsigned)R, R1 = Ru + 1u;
        int dns = lp.dense[l];
        const float2* tabL = (const float2*)tab + (size_t)l * TSZ;
        float ax = 0.f, ay = 0.f;
#pragma unroll
        for (int c = 0; c < 8; c++) {
            unsigned ox = c & 1, oy = (c >> 1) & 1, oz = (c >> 2) & 1;
            unsigned ix = min(ux + ox, Ru);
            unsigned iy = min(uy + oy, Ru);
            unsigned iz = min(uz + oz, Ru);
            unsigned flat;
            if (dns) flat = ix + R1 * (iy + R1 * iz);
            else     flat = (ix ^ (iy * P1) ^ (iz * P2)) & (TSZ - 1u);
            float wc = wx[ox] * wy[oy] * wz[oz];
            float2 tv = __ldg(&tabL[flat]);
            ax = fmaf(wc, tv.x, ax);
            ay = fmaf(wc, tv.y, ay);
        }
        vals[39 + 2 * l] = ax;
        vals[40 + 2 * l] = ay;
    }

    // vectorized fp16 store: 9 x uint4 (cols 0..71)
    __half* Fh = F + (size_t)i * KP0;
#pragma unroll
    for (int c0 = 0; c0 < 72; c0 += 8) {
        uint32 w[4];
#pragma unroll
        for (int q = 0; q < 4; q++) {
            __half2 hv = __floats2half2_rn(vals[c0 + 2 * q], vals[c0 + 2 * q + 1]);
            w[q] = *(uint32*)&hv;
        }
        *(uint4*)(Fh + c0) = make_uint4(w[0], w[1], w[2], w[3]);
    }
}

// ---------------- fp16 GEMM via mma.sync (HMMA), fp32 accumulate ----------------
// CTA tile 64(M) x 256(N full). 256 threads, 8 warps of 32x64. KC=64 chunks
// (NC = KPAD/64), 2-stage cp.async, one __syncthreads per chunk.
// LAST variant fuses the 257th output column via staged-A smem re-reads.
#define KC   64
#define RS   144                       // smem row stride bytes: (r+s) mod 8 bank perm
#define ATA  (64 * RS)                 // A tile array bytes  (9216)
#define ATB  (256 * RS)                // B tile array bytes  (36864)
#define STG  (ATA + ATB)               // per stage (46080)
#define SMEM_SZ (2 * STG)              // 92160 -> 2 CTAs/SM

template<int KPAD, bool ACT, bool LAST>
__global__ __launch_bounds__(256, 2)
void gemm_mma(const __half* __restrict__ A, const __half* __restrict__ B,
              const float* __restrict__ bias,
              const float* __restrict__ wlast,
              __half* __restrict__ O, float* __restrict__ Of)
{
    constexpr int NC = KPAD / KC;
    extern __shared__ char smem[];
    uint32 sb = smem_u32(smem);

    const int tid  = threadIdx.x;
    const int lane = tid & 31;
    const int wid  = tid >> 5;
    const int warpM = wid & 1;         // 0..1 -> 32-row slice
    const int warpN = wid >> 1;        // 0..3 -> 64-col slice
    const int mBase = blockIdx.x * 64;

    // loader mapping (16B chunks, KC=64 -> 8 slots/row):
    //   A: 64 rows x 8 = 512 -> 2/thread (rows ldRow, ldRow+32)
    //   B: 256 rows x 8 = 2048 -> 8/thread
    const int ldRow = tid >> 3, ldSlot = tid & 7;   // ldRow 0..31

    const char* pA = (const char*)(A + (size_t)mBase * KPAD);
    const char* pB = (const char*)B;

    auto issue_chunk = [&](int c) {
        uint32 stage = sb + (c & 1) * STG;
#pragma unroll
        for (int t = 0; t < 2; t++) {
            int row = ldRow + t * 32;
            size_t ga = (size_t)row * (KPAD * 2) + c * (KC * 2) + ldSlot * 16;
            CP_ASYNC16(stage + row * RS + ldSlot * 16, pA + ga);
        }
#pragma unroll
        for (int t = 0; t < 8; t++) {
            int row = ldRow + t * 32;
            size_t gb = (size_t)row * (KPAD * 2) + c * (KC * 2) + ldSlot * 16;
            CP_ASYNC16(stage + ATA + row * RS + ldSlot * 16, pB + gb);
        }
        CP_COMMIT();
    };

    float acc[2][8][4];
#pragma unroll
    for (int mt = 0; mt < 2; mt++)
#pragma unroll
        for (int nt = 0; nt < 8; nt++)
#pragma unroll
            for (int q = 0; q < 4; q++) acc[mt][nt][q] = 0.f;

    float accL0 = 0.f, accL1 = 0.f;    // fused 257th-column dots (LAST only)

    const uint32 aOff = (uint32)(warpM * 32 + (lane & 15)) * RS + (lane >> 4) * 16;
    const uint32 bOff = (uint32)(warpN * 64 + (lane & 7) + ((lane >> 4) << 3)) * RS
                        + ((lane >> 3) & 1) * 16;

    issue_chunk(0);

    for (int c = 0; c < NC; c++) {
        // chunk c is the only group in flight; wait, then the barrier publishes
        // its data AND certifies compute of c-1 finished (buffer (c+1)&1 free).
        CP_WAIT(0);
        __syncthreads();
        if (c + 1 < NC) issue_chunk(c + 1);   // overlaps compute of chunk c

        uint32 stage = sb + (c & 1) * STG;
        uint32 sA = stage + aOff;
        uint32 sB = stage + ATA + bOff;

        if (LAST) {
            // re-read this thread's own staged A chunks (rows ldRow, ldRow+32)
            const float* wsp = wlast + c * KC + ldSlot * 8;
#pragma unroll
            for (int t = 0; t < 2; t++) {
                uint32 aAddr = stage + (ldRow + t * 32) * RS + ldSlot * 16;
                uint32 av0, av1, av2, av3;
                asm volatile("ld.shared.v4.u32 {%0,%1,%2,%3}, [%4];"
                             : "=r"(av0), "=r"(av1), "=r"(av2), "=r"(av3) : "r"(aAddr));
                uint32 avw[4] = {av0, av1, av2, av3};
                float accv = 0.f;
#pragma unroll
                for (int j = 0; j < 4; j++) {
                    __half2 h = *(__half2*)&avw[j];
                    float2 f = __half22float2(h);
                    accv = fmaf(f.x, __ldg(wsp + 2 * j),     accv);
                    accv = fmaf(f.y, __ldg(wsp + 2 * j + 1), accv);
                }
                if (t == 0) accL0 += accv; else accL1 += accv;
            }
        }

#pragma unroll
        for (int ks = 0; ks < 4; ks++) {
            uint32 kb = ks * 32;               // 16 k-elems = 32 bytes
            uint32 a[2][4];
            LDSM4(a[0][0], a[0][1], a[0][2], a[0][3], sA + kb);
            LDSM4(a[1][0], a[1][1], a[1][2], a[1][3], sA + 16 * RS + kb);
#pragma unroll
            for (int np = 0; np < 4; np++) {
                uint32 b[4];
                LDSM4(b[0], b[1], b[2], b[3], sB + np * 16 * RS + kb);
#pragma unroll
                for (int mt = 0; mt < 2; mt++) {
                    MMA16816(acc[mt][2 * np + 0], a[mt][0], a[mt][1], a[mt][2], a[mt][3], b[0], b[1]);
                    MMA16816(acc[mt][2 * np + 1], a[mt][0], a[mt][1], a[mt][2], a[mt][3], b[2], b[3]);
                }
            }
        }
    }

    // ---------------- fused last column: reduce across the 8 slot-threads -------
    if (LAST) {
        // threads with the same ldRow are 8 consecutive lanes (slot = low 3 bits)
        accL0 += __shfl_xor_sync(0xffffffffu, accL0, 1);
        accL0 += __shfl_xor_sync(0xffffffffu, accL0, 2);
        accL0 += __shfl_xor_sync(0xffffffffu, accL0, 4);
        accL1 += __shfl_xor_sync(0xffffffffu, accL1, 1);
        accL1 += __shfl_xor_sync(0xffffffffu, accL1, 2);
        accL1 += __shfl_xor_sync(0xffffffffu, accL1, 4);
        if (ldSlot == 0) {
            float blast = __ldg(bias + 256);
            Of[(size_t)(mBase + ldRow)      * 257 + 256] = accL0 + blast;
            Of[(size_t)(mBase + ldRow + 32) * 257 + 256] = accL1 + blast;
        }
    }

    // ---------------- epilogue: bias + act + store ------------------------------
#pragma unroll
    for (int mt = 0; mt < 2; mt++) {
        int m0 = mBase + warpM * 32 + mt * 16 + (lane >> 2);
#pragma unroll
        for (int nt = 0; nt < 8; nt++) {
            int n0 = warpN * 64 + nt * 8 + (lane & 3) * 2;
            float bj0 = __ldg(bias + n0), bj1 = __ldg(bias + n0 + 1);
#pragma unroll
            for (int half = 0; half < 2; half++) {
                int m = m0 + half * 8;
                float v0 = acc[mt][nt][2 * half + 0] + bj0;
                float v1 = acc[mt][nt][2 * half + 1] + bj1;
                if (ACT) { v0 = softplus100(v0); v1 = softplus100(v1); }
                if (LAST) {
                    float* orow = Of + (size_t)m * 257 + n0;
                    orow[0] = v0; orow[1] = v1;
                } else {
                    __half2 hv = __floats2half2_rn(v0, v1);
                    *(__half2*)(O + (size_t)m * 256 + n0) = hv;
                }
            }
        }
    }
}

// ---------------- launch --------------------------------------------------------
extern "C" void kernel_launch(void* const* d_in, const int* in_sizes, int n_in,
                              void* d_out, int out_size)
{
    const float* x      = (const float*)d_in[0];
    const float* tables = (const float*)d_in[1];
    const float* v0 = (const float*)d_in[2];
    const float* g0 = (const float*)d_in[3];
    const float* b0 = (const float*)d_in[4];
    const float* v1 = (const float*)d_in[5];
    const float* g1 = (const float*)d_in[6];
    const float* b1 = (const float*)d_in[7];
    const float* v2 = (const float*)d_in[8];
    const float* g2 = (const float*)d_in[9];
    const float* b2 = (const float*)d_in[10];
    float* out = (float*)d_out;

    __half *F, *H0, *H1, *W0, *W1, *W2;
    float* w2last;
    cudaGetSymbolAddress((void**)&F,  g_F);
    cudaGetSymbolAddress((void**)&H0, g_H0);
    cudaGetSymbolAddress((void**)&H1, g_H1);
    cudaGetSymbolAddress((void**)&W0, g_W0);
    cudaGetSymbolAddress((void**)&W1, g_W1);
    cudaGetSymbolAddress((void**)&W2, g_W2);
    cudaGetSymbolAddress((void**)&w2last, g_w2last);

    LevelParams lp;
    double SCALE = pow(2.0, log2(2048.0 / 16.0) / 15.0);
    for (int l = 0; l < 16; l++) {
        int R = (int)ceil(16.0 * pow(SCALE, (double)l));
        lp.R[l] = R;
        long long cc = (long long)R + 1;
        lp.dense[l] = (cc * cc * cc <= (long long)TSZ) ? 1 : 0;
    }

    cudaFuncSetAttribute(gemm_mma<KP0, true,  false>, cudaFuncAttributeMaxDynamicSharedMemorySize, SMEM_SZ);
    cudaFuncSetAttribute(gemm_mma<256, true,  false>, cudaFuncAttributeMaxDynamicSharedMemorySize, SMEM_SZ);
    cudaFuncSetAttribute(gemm_mma<256, false, true >, cudaFuncAttributeMaxDynamicSharedMemorySize, SMEM_SZ);

    prep_weights_tc<<<256, 256>>>(v0, g0, 71,  KP0, W0, nullptr);
    prep_weights_tc<<<256, 256>>>(v1, g1, 256, 256, W1, nullptr);
    prep_weights_tc<<<257, 256>>>(v2, g2, 256, 256, W2, w2last);

    encode_kernel<<<NPTS / 256, 256>>>(x, tables, F, lp);

    gemm_mma<KP0, true,  false><<<NPTS / 64, 256, SMEM_SZ>>>(F,  W0, b0, nullptr, H0, nullptr);
    gemm_mma<256, true,  false><<<NPTS / 64, 256, SMEM_SZ>>>(H0, W1, b1, nullptr, H1, nullptr);
    gemm_mma<256, false, true ><<<NPTS / 64, 256, SMEM_SZ>>>(H1, W2, b2, w2last, nullptr, out);
}